// round 13
// baseline (speedup 1.0000x reference)
#include <cuda_runtime.h>
#include <cuda_bf16.h>
#include <math.h>

#define FULLMASK 0xffffffffu

constexpr int T_ = 128;
constexpr int H_ = 128;
constexpr float EPS_ = 1e-5f;

__device__ float g_emb[1024 * 128 * 128];
__device__ float g_pj[1024 * 128 * 8];

__device__ __forceinline__ float warp_sum(float v) {
    v += __shfl_xor_sync(FULLMASK, v, 16);
    v += __shfl_xor_sync(FULLMASK, v, 8);
    v += __shfl_xor_sync(FULLMASK, v, 4);
    v += __shfl_xor_sync(FULLMASK, v, 2);
    v += __shfl_xor_sync(FULLMASK, v, 1);
    return v;
}
__device__ __forceinline__ float sigf(float x)  { return 1.f / (1.f + __expf(-x)); }
__device__ __forceinline__ float tanhff(float x){ return 1.f - 2.f / (1.f + __expf(2.f * x)); }

__device__ __forceinline__ float2 ffma2(float2 a, float2 b, float2 c) {
    float2 d;
    asm("fma.rn.f32x2 %0, %1, %2, %3;"
        : "=l"(reinterpret_cast<unsigned long long&>(d))
        : "l"(reinterpret_cast<unsigned long long&>(a)),
          "l"(reinterpret_cast<unsigned long long&>(b)),
          "l"(reinterpret_cast<unsigned long long&>(c)));
    return d;
}
__device__ __forceinline__ float2 fmul2(float2 a, float2 b) {
    float2 d;
    asm("mul.rn.f32x2 %0, %1, %2;"
        : "=l"(reinterpret_cast<unsigned long long&>(d))
        : "l"(reinterpret_cast<unsigned long long&>(a)),
          "l"(reinterpret_cast<unsigned long long&>(b)));
    return d;
}

// 8-value keep/send butterfly sum over 32 lanes.
// Input: d[8] per-lane partials (pre-reduced over masks 2,1 by caller).
// Output: full sum of row j at lanes with (lane>>2)&7 == j.
__device__ __forceinline__ float bfly8(const float* d, int lane) {
    bool hi = lane & 16;
    float s0 = hi ? d[0] : d[4]; float r0 = __shfl_xor_sync(FULLMASK, s0, 16);
    float s1 = hi ? d[1] : d[5]; float r1 = __shfl_xor_sync(FULLMASK, s1, 16);
    float s2 = hi ? d[2] : d[6]; float r2 = __shfl_xor_sync(FULLMASK, s2, 16);
    float s3 = hi ? d[3] : d[7]; float r3 = __shfl_xor_sync(FULLMASK, s3, 16);
    float a0 = (hi ? d[4] : d[0]) + r0;
    float a1 = (hi ? d[5] : d[1]) + r1;
    float a2 = (hi ? d[6] : d[2]) + r2;
    float a3 = (hi ? d[7] : d[3]) + r3;
    bool h8 = lane & 8;
    float t0 = h8 ? a0 : a2; float q0 = __shfl_xor_sync(FULLMASK, t0, 8);
    float t1 = h8 ? a1 : a3; float q1 = __shfl_xor_sync(FULLMASK, t1, 8);
    float b0 = (h8 ? a2 : a0) + q0;
    float b1 = (h8 ? a3 : a1) + q1;
    bool h4 = lane & 4;
    float u = h4 ? b0 : b1; float p = __shfl_xor_sync(FULLMASK, u, 4);
    return (h4 ? b1 : b0) + p;
}

__global__ __launch_bounds__(64, 7)
void qlstm_kernel(
    const float* __restrict__ x,     const float* __restrict__ pe,
    const float* __restrict__ emb_w, const float* __restrict__ emb_b,
    const float* __restrict__ emb_g, const float* __restrict__ emb_bt,
    const float* __restrict__ ip_w,  const float* __restrict__ ip_b,
    const float* __restrict__ in_g,  const float* __restrict__ in_b,
    const float* __restrict__ wq_i,  const float* __restrict__ wq_f,
    const float* __restrict__ wq_g,  const float* __restrict__ wq_o,
    const float* __restrict__ pi_w,  const float* __restrict__ pi_b,
    const float* __restrict__ pf_w,  const float* __restrict__ pf_b,
    const float* __restrict__ pg_w,  const float* __restrict__ pg_b,
    const float* __restrict__ po_w,  const float* __restrict__ po_b,
    const float* __restrict__ on_g,  const float* __restrict__ on_b,
    const float* __restrict__ out_w, const float* __restrict__ out_b,
    float* __restrict__ out)
{
    const int e = blockIdx.x;
    const int tid = threadIdx.x, w = tid >> 5, lane = tid & 31;
    const int ll = lane & 15;
    const int gate = 2 * w + (lane >> 4);

    __shared__ __align__(16) float sx[1024];       // x staging (prologue)
    __shared__ __align__(16) float sipw[8][128];   // ip_w emb-half (prologue)
    __shared__ float sipb[8];
    __shared__ __align__(16) float  sh_hs[128];
    __shared__ __align__(16) float  sh_wct[4][4][8];
    __shared__ __align__(16) float4 sh_z[4][2];
    __shared__ float sh_redf[2][4];
    __shared__ float sh_sc[2], sh_ing8[8], sh_inb8[8];

    // =============== staging ===============
    {
        const float4* xg = (const float4*)(x + (size_t)e * 1024);
        #pragma unroll
        for (int i = 0; i < 4; i++) ((float4*)sx)[tid + i * 64] = xg[tid + i * 64];
        const float4* iw4 = (const float4*)ip_w;
        #pragma unroll
        for (int i = 0; i < 4; i++) {
            int idx = tid + i * 64;            // 0..255
            int j = idx >> 5, c = idx & 31;    // row j, float4-col c (emb half)
            ((float4*)sipw)[idx] = iw4[j * 64 + c];
        }
        if (tid < 8) { sipb[tid] = ip_b[tid]; sh_ing8[tid] = in_g[tid]; sh_inb8[tid] = in_b[tid]; }
        const float* wqp[4] = {wq_i, wq_f, wq_g, wq_o};
        #pragma unroll
        for (int i = tid; i < 128; i += 64) {
            int g = i >> 5, rem = i & 31, lyr = rem >> 3, q = rem & 7;
            sh_wct[g][lyr][q] = tanf(0.5f * wqp[g][lyr * 8 + q]);
        }
        sh_hs[tid] = 0.f; sh_hs[tid + 64] = 0.f;
    }

    // per-thread constants
    float cw2g;
    {
        const float* wqp[4] = {wq_i, wq_f, wq_g, wq_o};
        float cw = 1.f;
        #pragma unroll
        for (int k = 0; k < 32; k++) cw *= cosf(0.5f * wqp[gate][k]);
        cw2g = cw * cw;
    }
    float wbr[8][4];
    #pragma unroll
    for (int jj = 0; jj < 8; jj++)
        #pragma unroll
        for (int i = 0; i < 4; i++)
            wbr[jj][i] = ip_w[jj * 256 + 128 + lane + 32 * i];
    float pwr[2][32], bia[2][4];
    {
        const float* pw[4] = {pi_w, pf_w, pg_w, po_w};
        const float* pb[4] = {pi_b, pf_b, pg_b, po_b};
        #pragma unroll
        for (int hh = 0; hh < 2; hh++) {
            int h = tid + 64 * hh;
            #pragma unroll
            for (int g = 0; g < 4; g++) {
                bia[hh][g] = pb[g][h];
                #pragma unroll
                for (int q = 0; q < 8; q++) pwr[hh][g*8+q] = pw[g][h*8+q];
            }
        }
    }
    float gw0 = on_g[tid]*out_w[tid],     gw1 = on_g[tid+64]*out_w[tid+64];
    float bw0 = on_b[tid]*out_w[tid],     bw1 = on_b[tid+64]*out_w[tid+64];
    {
        float s1 = warp_sum(gw0 + gw1), s2 = warp_sum(bw0 + bw1);
        if (lane == 0) { sh_redf[w][0] = s1; sh_redf[w][1] = s2; }
    }
    __syncthreads();

    // =============== prologue: emb + LN + pe, and emb-half proj dot ===============
    {
        float ew[4][8], gbv[4], btv[4], bbv[4];
        #pragma unroll
        for (int m = 0; m < 4; m++) {
            int h = lane + 32 * m;
            #pragma unroll
            for (int k = 0; k < 8; k++) ew[m][k] = emb_w[h * 8 + k];
            gbv[m] = emb_g[h]; btv[m] = emb_bt[h]; bbv[m] = emb_b[h];
        }
        float* embdst = g_emb + (size_t)e * T_ * H_;
        float* pjdst  = g_pj  + (size_t)e * T_ * 8;
        for (int it = 0; it < 64; it++) {
            int t = it * 2 + w;
            const float* xr = sx + t * 8;
            float e4[4];
            #pragma unroll
            for (int m = 0; m < 4; m++) {
                float s = bbv[m];
                #pragma unroll
                for (int k = 0; k < 8; k++) s += xr[k] * ew[m][k];
                e4[m] = s;
            }
            float s = (e4[0]+e4[1])+(e4[2]+e4[3]);
            float q = (e4[0]*e4[0]+e4[1]*e4[1])+(e4[2]*e4[2]+e4[3]*e4[3]);
            s += __shfl_xor_sync(FULLMASK, s, 16);
            q += __shfl_xor_sync(FULLMASK, q, 16);
            float u = (lane & 16) ? q : s;
            u += __shfl_xor_sync(FULLMASK, u, 8);
            u += __shfl_xor_sync(FULLMASK, u, 4);
            u += __shfl_xor_sync(FULLMASK, u, 2);
            u += __shfl_xor_sync(FULLMASK, u, 1);
            float other = __shfl_xor_sync(FULLMASK, u, 16);
            float sf = (lane & 16) ? other : u;
            float qf = (lane & 16) ? u : other;
            float m_ = sf * (1.f/128.f);
            float inv = rsqrtf(qf * (1.f/128.f) - m_*m_ + EPS_);
            float val[4];
            #pragma unroll
            for (int m = 0; m < 4; m++) {
                int h = lane + 32 * m;
                val[m] = (e4[m]-m_)*inv*gbv[m] + btv[m] + __ldg(pe + t*H_ + h);
                embdst[t*H_ + h] = val[m];
            }
            float d[8];
            #pragma unroll
            for (int jj = 0; jj < 8; jj++) {
                float dv = 0.f;
                #pragma unroll
                for (int m = 0; m < 4; m++) dv += val[m] * sipw[jj][lane + 32*m];
                dv += __shfl_xor_sync(FULLMASK, dv, 2);
                dv += __shfl_xor_sync(FULLMASK, dv, 1);
                d[jj] = dv;
            }
            float v = bfly8(d, lane);
            if ((lane & 3) == 0) {
                int j = (lane >> 2) & 7;
                pjdst[t * 8 + j] = v + sipb[j];
            }
        }
    }
    __syncthreads();
    if (tid == 0) {
        sh_sc[0] = sh_redf[0][0] + sh_redf[1][0];
        sh_sc[1] = sh_redf[0][1] + sh_redf[1][1] + out_b[0];
    }
    __syncthreads();
    const float S1 = sh_sc[0], C0 = sh_sc[1];

    // virtual-permutation constants (F^4 = I), packed into vmask
    const int SM_[4][4] = {{8,12,14,3},{8,4,10,13},{8,12,6,7},{8,4,2,1}};
    const int C3M[4]    = {3,13,7,1};
    unsigned vmask = 0;
    #pragma unroll
    for (int k = 0; k < 4; k++) {
        #pragma unroll
        for (int q = 0; q < 4; q++)
            vmask |= (unsigned)(__popc(lane & SM_[k][q]) & 1) << (k*4+q);
        vmask |= (unsigned)(__popc(lane & C3M[k]) & 1) << (16+k);
    }

    float h_c[2] = {0.f, 0.f}, c_c[2] = {0.f, 0.f};
    const float* embrow = g_emb + (size_t)e * T_ * H_;
    const float* pjrow  = g_pj  + (size_t)e * T_ * 8;

    float pj_carry = pjrow[lane & 7];   // row (lane&7), t=0 (plain load: self-written)

    for (int t = 0; t < T_; t++) {
        float emb0 = embrow[t * H_ + tid];
        float emb1 = embrow[t * H_ + tid + 64];

        // ---- Phase B (redundant in both warps; NO barrier before LN) ----
        float pv_in;
        {
            float hv0 = sh_hs[lane],      hv1 = sh_hs[lane + 32];
            float hv2 = sh_hs[lane + 64], hv3 = sh_hs[lane + 96];
            float d[8];
            #pragma unroll
            for (int jj = 0; jj < 8; jj++) {
                float dv = hv0*wbr[jj][0] + hv1*wbr[jj][1] + hv2*wbr[jj][2] + hv3*wbr[jj][3];
                dv += __shfl_xor_sync(FULLMASK, dv, 2);
                dv += __shfl_xor_sync(FULLMASK, dv, 1);
                d[jj] = dv;
            }
            float v = bfly8(d, lane);
            float tgv = __shfl_sync(FULLMASK, v, (lane & 7) << 2);
            pv_in = tgv + pj_carry;
            int tn = (t < 127) ? t + 1 : 127;
            pj_carry = pjrow[tn * 8 + (lane & 7)];
        }

        // ---- mini-LN(8) + angles (redundant per warp) ----
        float scl;
        float F0[8], F1[8];
        {
            float pv = tanhff(pv_in);
            float sm_ = pv, sq = pv*pv;
            sm_ += __shfl_xor_sync(FULLMASK, sm_, 1); sq += __shfl_xor_sync(FULLMASK, sq, 1);
            sm_ += __shfl_xor_sync(FULLMASK, sm_, 2); sq += __shfl_xor_sync(FULLMASK, sq, 2);
            sm_ += __shfl_xor_sync(FULLMASK, sm_, 4); sq += __shfl_xor_sync(FULLMASK, sq, 4);
            float mm = sm_ * 0.125f;
            float iv = rsqrtf(sq * 0.125f - mm*mm + EPS_);
            int q = lane & 7;
            float a = 0.5f * ((pv - mm) * iv * sh_ing8[q] + sh_inb8[q]);
            float ss, cc; __sincosf(a, &ss, &cc);
            float tq = __fdividef(ss, cc);
            cc *= __shfl_xor_sync(FULLMASK, cc, 1);
            cc *= __shfl_xor_sync(FULLMASK, cc, 2);
            cc *= __shfl_xor_sync(FULLMASK, cc, 4);
            float cin = cc * 0.0625f;
            scl = cin * cin * cw2g;
            int base = lane & 24;
            #pragma unroll
            for (int q2 = 0; q2 < 8; q2++) {
                float tg = __shfl_sync(FULLMASK, tq, base | q2);
                F0[q2] = 1.f - tg; F1[q2] = 1.f + tg;
            }
        }

        // ---- Phase C: VQC (tan-form, virtual perm, f32x2) ----
        float2 st2[8];
        {
            float v0 = ((ll&8)?F1[0]:F0[0]) * ((ll&4)?F1[1]:F0[1])
                     * ((ll&2)?F1[2]:F0[2]) * ((ll&1)?F1[3]:F0[3]);
            float a0 = v0 * F0[4], a8 = v0 * F1[4];
            float b0 = a0*F0[5], b4 = a0*F1[5], b8 = a8*F0[5], b12 = a8*F1[5];
            float c0=b0*F0[6], c2=b0*F1[6], c4=b4*F0[6], c6=b4*F1[6];
            float c8=b8*F0[6], c10=b8*F1[6], c12=b12*F0[6], c14=b12*F1[6];
            st2[0]=make_float2(c0*F0[7],  c0*F1[7]);  st2[1]=make_float2(c2*F0[7],  c2*F1[7]);
            st2[2]=make_float2(c4*F0[7],  c4*F1[7]);  st2[3]=make_float2(c6*F0[7],  c6*F1[7]);
            st2[4]=make_float2(c8*F0[7],  c8*F1[7]);  st2[5]=make_float2(c10*F0[7], c10*F1[7]);
            st2[6]=make_float2(c12*F0[7], c12*F1[7]); st2[7]=make_float2(c14*F0[7], c14*F1[7]);
        }

        const int BM[4][4] = {{12,7,3,1},{11,5,2,1},{14,6,3,1},{8,4,2,1}};
        #pragma unroll
        for (int lyr = 0; lyr < 4; lyr++) {
            // c4
            { float2 tp = st2[4]; st2[4] = st2[6]; st2[6] = tp;
              tp = st2[5]; st2[5] = st2[7]; st2[7] = tp; }
            // c6
            { float tp;
              tp = st2[1].x; st2[1].x = st2[1].y; st2[1].y = tp;
              tp = st2[3].x; st2[3].x = st2[3].y; st2[3].y = tp;
              tp = st2[5].x; st2[5].x = st2[5].y; st2[5].y = tp;
              tp = st2[7].x; st2[7].x = st2[7].y; st2[7].y = tp; }
            // c5
            { float2 tp = st2[2]; st2[2] = st2[3]; st2[3] = tp;
              tp = st2[6]; st2[6] = st2[7]; st2[7] = tp; }
            // c3 (virtual-layout parity control)
            {
                bool cc3 = (vmask >> (16 + lyr)) & 1;
                #pragma unroll
                for (int j = 0; j < 4; j++) {
                    float2 a = st2[j], b = st2[j+4];
                    st2[j].x   = cc3 ? b.x : a.x;  st2[j].y   = cc3 ? b.y : a.y;
                    st2[j+4].x = cc3 ? a.x : b.x;  st2[j+4].y = cc3 ? a.y : b.y;
                }
            }
            // lane-qubit RYs q0..q3 (layout-transformed masks, sign from vmask)
            const float4 tl4 = *(const float4*)&sh_wct[gate][lyr][0];
            #pragma unroll
            for (int q = 0; q < 4; q++) {
                const int bm = BM[lyr][q];
                float tabs = (q == 0) ? tl4.x : (q == 1) ? tl4.y : (q == 2) ? tl4.z : tl4.w;
                float tq = ((vmask >> (lyr*4+q)) & 1) ? tabs : -tabs;
                #pragma unroll
                for (int j = 0; j < 8; j++) {
                    float ox = __shfl_xor_sync(FULLMASK, st2[j].x, bm);
                    float oy = __shfl_xor_sync(FULLMASK, st2[j].y, bm);
                    st2[j].x = fmaf(tq, ox, st2[j].x);
                    st2[j].y = fmaf(tq, oy, st2[j].y);
                }
            }
            // reg-qubit RYs q4..q7
            const float4 tl = *(const float4*)&sh_wct[gate][lyr][4];
            {
                float2 nt = make_float2(-tl.x, -tl.x), pt = make_float2(tl.x, tl.x);
                #pragma unroll
                for (int j = 0; j < 4; j++) {
                    float2 lo = st2[j], hi = st2[j+4];
                    st2[j]   = ffma2(nt, hi, lo);
                    st2[j+4] = ffma2(pt, lo, hi);
                }
            }
            {
                float2 nt = make_float2(-tl.y, -tl.y), pt = make_float2(tl.y, tl.y);
                #pragma unroll
                for (int j = 0; j < 8; j++) if (!(j & 2)) {
                    float2 lo = st2[j], hi = st2[j+2];
                    st2[j]   = ffma2(nt, hi, lo);
                    st2[j+2] = ffma2(pt, lo, hi);
                }
            }
            {
                float2 nt = make_float2(-tl.z, -tl.z), pt = make_float2(tl.z, tl.z);
                #pragma unroll
                for (int j = 0; j < 8; j += 2) {
                    float2 lo = st2[j], hi = st2[j+1];
                    st2[j]   = ffma2(nt, hi, lo);
                    st2[j+1] = ffma2(pt, lo, hi);
                }
            }
            {
                float tq = tl.w;
                #pragma unroll
                for (int j = 0; j < 8; j++) {
                    float a0 = st2[j].x, a1 = st2[j].y;
                    st2[j].x = fmaf(-tq, a1, a0);
                    st2[j].y = fmaf( tq, a0, a1);
                }
            }
        }

        // ---- measurement ----
        {
            float2 p2[8];
            #pragma unroll
            for (int j = 0; j < 8; j++) p2[j] = fmul2(st2[j], st2[j]);
            float s8[8], s4[4], s2[2];
            float z7=0, z6=0, z5=0;
            #pragma unroll
            for (int k = 0; k < 8; k++) { s8[k] = p2[k].x + p2[k].y; z7 += p2[k].x - p2[k].y; }
            #pragma unroll
            for (int k = 0; k < 4; k++) { s4[k] = s8[2*k]+s8[2*k+1]; z6 += s8[2*k]-s8[2*k+1]; }
            #pragma unroll
            for (int k = 0; k < 2; k++) { s2[k] = s4[2*k]+s4[2*k+1]; z5 += s4[2*k]-s4[2*k+1]; }
            float z4 = s2[0]-s2[1], Tt = s2[0]+s2[1];
            float o, z0v, z1v, z2v, z3v;

            o = __shfl_xor_sync(FULLMASK, Tt, 1);
            z3v = (lane & 1) ? (o - Tt) : (Tt - o); Tt += o;
            z4 += __shfl_xor_sync(FULLMASK, z4, 1);
            z5 += __shfl_xor_sync(FULLMASK, z5, 1);
            z6 += __shfl_xor_sync(FULLMASK, z6, 1);
            z7 += __shfl_xor_sync(FULLMASK, z7, 1);

            o = __shfl_xor_sync(FULLMASK, Tt, 2);
            z2v = (lane & 2) ? (o - Tt) : (Tt - o); Tt += o;
            z3v += __shfl_xor_sync(FULLMASK, z3v, 2);
            z4 += __shfl_xor_sync(FULLMASK, z4, 2);
            z5 += __shfl_xor_sync(FULLMASK, z5, 2);
            z6 += __shfl_xor_sync(FULLMASK, z6, 2);
            z7 += __shfl_xor_sync(FULLMASK, z7, 2);

            o = __shfl_xor_sync(FULLMASK, Tt, 4);
            z1v = (lane & 4) ? (o - Tt) : (Tt - o); Tt += o;
            z2v += __shfl_xor_sync(FULLMASK, z2v, 4);
            z3v += __shfl_xor_sync(FULLMASK, z3v, 4);
            z4 += __shfl_xor_sync(FULLMASK, z4, 4);
            z5 += __shfl_xor_sync(FULLMASK, z5, 4);
            z6 += __shfl_xor_sync(FULLMASK, z6, 4);
            z7 += __shfl_xor_sync(FULLMASK, z7, 4);

            o = __shfl_xor_sync(FULLMASK, Tt, 8);
            z0v = (lane & 8) ? (o - Tt) : (Tt - o);
            z1v += __shfl_xor_sync(FULLMASK, z1v, 8);
            z2v += __shfl_xor_sync(FULLMASK, z2v, 8);
            z3v += __shfl_xor_sync(FULLMASK, z3v, 8);
            z4 += __shfl_xor_sync(FULLMASK, z4, 8);
            z5 += __shfl_xor_sync(FULLMASK, z5, 8);
            z6 += __shfl_xor_sync(FULLMASK, z6, 8);
            z7 += __shfl_xor_sync(FULLMASK, z7, 8);

            if (ll == 0) {
                sh_z[gate][0] = make_float4(z0v*scl, z1v*scl, z2v*scl, z3v*scl);
                sh_z[gate][1] = make_float4(z4*scl, z5*scl, z6*scl, z7*scl);
            }
        }
        __syncthreads();

        // ---- Phase D ----
        {
            float4 zr[4][2];
            #pragma unroll
            for (int g = 0; g < 4; g++) { zr[g][0] = sh_z[g][0]; zr[g][1] = sh_z[g][1]; }
            float v[2];
            #pragma unroll
            for (int hh = 0; hh < 2; hh++) {
                float pre[4];
                #pragma unroll
                for (int g = 0; g < 4; g++) {
                    float4 z0 = zr[g][0], z1 = zr[g][1];
                    const float* pw = &pwr[hh][g*8];
                    pre[g] = bia[hh][g]
                           + z0.x*pw[0] + z0.y*pw[1] + z0.z*pw[2] + z0.w*pw[3]
                           + z1.x*pw[4] + z1.y*pw[5] + z1.z*pw[6] + z1.w*pw[7];
                }
                float i_t = sigf(pre[0]);
                float f_t = sigf(pre[1]);
                float g_t = tanhff(pre[2]);
                float o_t = sigf(pre[3]);
                c_c[hh] = f_t*c_c[hh] + i_t*g_t;
                h_c[hh] = o_t*tanhff(c_c[hh]);
                v[hh] = h_c[hh] + (hh ? emb1 : emb0);
            }
            sh_hs[tid] = h_c[0]; sh_hs[tid + 64] = h_c[1];
            float r0 = v[0] + v[1];
            float r1 = v[0]*v[0] + v[1]*v[1];
            float r2 = v[0]*gw0 + v[1]*gw1;
            r0 += __shfl_xor_sync(FULLMASK, r0, 16);
            r1 += __shfl_xor_sync(FULLMASK, r1, 16);
            r2 += __shfl_xor_sync(FULLMASK, r2, 16);
            r0 += __shfl_xor_sync(FULLMASK, r0, 8);
            r1 += __shfl_xor_sync(FULLMASK, r1, 8);
            r2 += __shfl_xor_sync(FULLMASK, r2, 8);
            int grp = lane >> 3;
            float vv = (grp == 0) ? r0 : (grp == 1) ? r1 : r2;
            vv += __shfl_xor_sync(FULLMASK, vv, 4);
            vv += __shfl_xor_sync(FULLMASK, vv, 2);
            vv += __shfl_xor_sync(FULLMASK, vv, 1);
            if ((lane & 7) == 0 && grp < 3) sh_redf[w][grp] = vv;
        }
        __syncthreads();
        if (tid == 0) {
            float Sv = sh_redf[0][0] + sh_redf[1][0];
            float Sq = sh_redf[0][1] + sh_redf[1][1];
            float Sg = sh_redf[0][2] + sh_redf[1][2];
            float m2 = Sv * (1.f/128.f);
            float inv2 = rsqrtf(Sq * (1.f/128.f) - m2*m2 + EPS_);
            out[(size_t)e * T_ + t] = inv2 * (Sg - m2 * S1) + C0;
        }
    }
}

extern "C" void kernel_launch(void* const* d_in, const int* in_sizes, int n_in,
                              void* d_out, int out_size) {
    const float* p[26];
    for (int i = 0; i < 26; i++) p[i] = (const float*)d_in[i];
    qlstm_kernel<<<1024, 64>>>(
        p[0], p[1], p[2], p[3], p[4], p[5], p[6], p[7], p[8], p[9],
        p[10], p[11], p[12], p[13], p[14], p[15], p[16], p[17], p[18], p[19],
        p[20], p[21], p[22], p[23], p[24], p[25],
        (float*)d_out);
}

// round 14
// speedup vs baseline: 1.0307x; 1.0307x over previous
#include <cuda_runtime.h>
#include <cuda_bf16.h>
#include <math.h>

#define FULLMASK 0xffffffffu

constexpr int T_ = 128;
constexpr int H_ = 128;
constexpr float EPS_ = 1e-5f;

__device__ float g_emb[1024 * 128 * 128];
__device__ float g_pj[1024 * 128 * 8];

__device__ __forceinline__ float warp_sum(float v) {
    v += __shfl_xor_sync(FULLMASK, v, 16);
    v += __shfl_xor_sync(FULLMASK, v, 8);
    v += __shfl_xor_sync(FULLMASK, v, 4);
    v += __shfl_xor_sync(FULLMASK, v, 2);
    v += __shfl_xor_sync(FULLMASK, v, 1);
    return v;
}
__device__ __forceinline__ float sigf(float x)  { return 1.f / (1.f + __expf(-x)); }
__device__ __forceinline__ float tanhff(float x){ return 1.f - 2.f / (1.f + __expf(2.f * x)); }

__device__ __forceinline__ float2 ffma2(float2 a, float2 b, float2 c) {
    float2 d;
    asm("fma.rn.f32x2 %0, %1, %2, %3;"
        : "=l"(reinterpret_cast<unsigned long long&>(d))
        : "l"(reinterpret_cast<unsigned long long&>(a)),
          "l"(reinterpret_cast<unsigned long long&>(b)),
          "l"(reinterpret_cast<unsigned long long&>(c)));
    return d;
}
__device__ __forceinline__ float2 fmul2(float2 a, float2 b) {
    float2 d;
    asm("mul.rn.f32x2 %0, %1, %2;"
        : "=l"(reinterpret_cast<unsigned long long&>(d))
        : "l"(reinterpret_cast<unsigned long long&>(a)),
          "l"(reinterpret_cast<unsigned long long&>(b)));
    return d;
}

// 8-value keep/send butterfly (PROLOGUE ONLY — off the critical step loop).
__device__ __forceinline__ float bfly8(const float* d, int lane) {
    bool hi = lane & 16;
    float s0 = hi ? d[0] : d[4]; float r0 = __shfl_xor_sync(FULLMASK, s0, 16);
    float s1 = hi ? d[1] : d[5]; float r1 = __shfl_xor_sync(FULLMASK, s1, 16);
    float s2 = hi ? d[2] : d[6]; float r2 = __shfl_xor_sync(FULLMASK, s2, 16);
    float s3 = hi ? d[3] : d[7]; float r3 = __shfl_xor_sync(FULLMASK, s3, 16);
    float a0 = (hi ? d[4] : d[0]) + r0;
    float a1 = (hi ? d[5] : d[1]) + r1;
    float a2 = (hi ? d[6] : d[2]) + r2;
    float a3 = (hi ? d[7] : d[3]) + r3;
    bool h8 = lane & 8;
    float t0 = h8 ? a0 : a2; float q0 = __shfl_xor_sync(FULLMASK, t0, 8);
    float t1 = h8 ? a1 : a3; float q1 = __shfl_xor_sync(FULLMASK, t1, 8);
    float b0 = (h8 ? a2 : a0) + q0;
    float b1 = (h8 ? a3 : a1) + q1;
    bool h4 = lane & 4;
    float u = h4 ? b0 : b1; float p = __shfl_xor_sync(FULLMASK, u, 4);
    return (h4 ? b1 : b0) + p;
}

__global__ __launch_bounds__(64, 7)
void qlstm_kernel(
    const float* __restrict__ x,     const float* __restrict__ pe,
    const float* __restrict__ emb_w, const float* __restrict__ emb_b,
    const float* __restrict__ emb_g, const float* __restrict__ emb_bt,
    const float* __restrict__ ip_w,  const float* __restrict__ ip_b,
    const float* __restrict__ in_g,  const float* __restrict__ in_b,
    const float* __restrict__ wq_i,  const float* __restrict__ wq_f,
    const float* __restrict__ wq_g,  const float* __restrict__ wq_o,
    const float* __restrict__ pi_w,  const float* __restrict__ pi_b,
    const float* __restrict__ pf_w,  const float* __restrict__ pf_b,
    const float* __restrict__ pg_w,  const float* __restrict__ pg_b,
    const float* __restrict__ po_w,  const float* __restrict__ po_b,
    const float* __restrict__ on_g,  const float* __restrict__ on_b,
    const float* __restrict__ out_w, const float* __restrict__ out_b,
    float* __restrict__ out)
{
    const int e = blockIdx.x;
    const int tid = threadIdx.x, w = tid >> 5, lane = tid & 31;
    const int ll = lane & 15;
    const int gate = 2 * w + (lane >> 4);

    __shared__ __align__(16) float sx[1024];       // x staging (prologue)
    __shared__ __align__(16) float sipw[8][128];   // ip_w emb-half (prologue)
    __shared__ float sipb[8];
    __shared__ __align__(16) float  sh_hs[128];
    __shared__ __align__(16) float  sh_wct[4][4][8];
    __shared__ __align__(16) float4 sh_pj4[2];
    __shared__ __align__(16) float4 sh_z[4][2];
    __shared__ float sh_redf[2][4];
    __shared__ float sh_sc[2], sh_ing8[8], sh_inb8[8];

    // =============== staging ===============
    {
        const float4* xg = (const float4*)(x + (size_t)e * 1024);
        #pragma unroll
        for (int i = 0; i < 4; i++) ((float4*)sx)[tid + i * 64] = xg[tid + i * 64];
        const float4* iw4 = (const float4*)ip_w;
        #pragma unroll
        for (int i = 0; i < 4; i++) {
            int idx = tid + i * 64;            // 0..255
            int j = idx >> 5, c = idx & 31;    // row j, float4-col c (emb half)
            ((float4*)sipw)[idx] = iw4[j * 64 + c];
        }
        if (tid < 8) { sipb[tid] = ip_b[tid]; sh_ing8[tid] = in_g[tid]; sh_inb8[tid] = in_b[tid]; }
        const float* wqp[4] = {wq_i, wq_f, wq_g, wq_o};
        #pragma unroll
        for (int i = tid; i < 128; i += 64) {
            int g = i >> 5, rem = i & 31, lyr = rem >> 3, q = rem & 7;
            sh_wct[g][lyr][q] = tanf(0.5f * wqp[g][lyr * 8 + q]);
        }
        sh_hs[tid] = 0.f; sh_hs[tid + 64] = 0.f;
    }

    // per-thread constants (R12 layout: 4 Phase-B rows per warp)
    float cw2g;
    {
        const float* wqp[4] = {wq_i, wq_f, wq_g, wq_o};
        float cw = 1.f;
        #pragma unroll
        for (int k = 0; k < 32; k++) cw *= cosf(0.5f * wqp[gate][k]);
        cw2g = cw * cw;
    }
    float wbr[4][4];
    #pragma unroll
    for (int jj = 0; jj < 4; jj++)
        #pragma unroll
        for (int i = 0; i < 4; i++)
            wbr[jj][i] = ip_w[(4*w + jj) * 256 + 128 + lane + 32 * i];
    float pwr[2][32], bia[2][4];
    {
        const float* pw[4] = {pi_w, pf_w, pg_w, po_w};
        const float* pb[4] = {pi_b, pf_b, pg_b, po_b};
        #pragma unroll
        for (int hh = 0; hh < 2; hh++) {
            int h = tid + 64 * hh;
            #pragma unroll
            for (int g = 0; g < 4; g++) {
                bia[hh][g] = pb[g][h];
                #pragma unroll
                for (int q = 0; q < 8; q++) pwr[hh][g*8+q] = pw[g][h*8+q];
            }
        }
    }
    float gw0 = on_g[tid]*out_w[tid],     gw1 = on_g[tid+64]*out_w[tid+64];
    float bw0 = on_b[tid]*out_w[tid],     bw1 = on_b[tid+64]*out_w[tid+64];
    {
        float s1 = warp_sum(gw0 + gw1), s2 = warp_sum(bw0 + bw1);
        if (lane == 0) { sh_redf[w][0] = s1; sh_redf[w][1] = s2; }
    }
    __syncthreads();

    // =============== prologue: emb + LN + pe, and emb-half proj dot ===============
    {
        float ew[4][8], gbv[4], btv[4], bbv[4];
        #pragma unroll
        for (int m = 0; m < 4; m++) {
            int h = lane + 32 * m;
            #pragma unroll
            for (int k = 0; k < 8; k++) ew[m][k] = emb_w[h * 8 + k];
            gbv[m] = emb_g[h]; btv[m] = emb_bt[h]; bbv[m] = emb_b[h];
        }
        float* embdst = g_emb + (size_t)e * T_ * H_;
        float* pjdst  = g_pj  + (size_t)e * T_ * 8;
        for (int it = 0; it < 64; it++) {
            int t = it * 2 + w;
            const float* xr = sx + t * 8;
            float e4[4];
            #pragma unroll
            for (int m = 0; m < 4; m++) {
                float s = bbv[m];
                #pragma unroll
                for (int k = 0; k < 8; k++) s += xr[k] * ew[m][k];
                e4[m] = s;
            }
            float s = (e4[0]+e4[1])+(e4[2]+e4[3]);
            float q = (e4[0]*e4[0]+e4[1]*e4[1])+(e4[2]*e4[2]+e4[3]*e4[3]);
            s += __shfl_xor_sync(FULLMASK, s, 16);
            q += __shfl_xor_sync(FULLMASK, q, 16);
            float u = (lane & 16) ? q : s;
            u += __shfl_xor_sync(FULLMASK, u, 8);
            u += __shfl_xor_sync(FULLMASK, u, 4);
            u += __shfl_xor_sync(FULLMASK, u, 2);
            u += __shfl_xor_sync(FULLMASK, u, 1);
            float other = __shfl_xor_sync(FULLMASK, u, 16);
            float sf = (lane & 16) ? other : u;
            float qf = (lane & 16) ? u : other;
            float m_ = sf * (1.f/128.f);
            float inv = rsqrtf(qf * (1.f/128.f) - m_*m_ + EPS_);
            float val[4];
            #pragma unroll
            for (int m = 0; m < 4; m++) {
                int h = lane + 32 * m;
                val[m] = (e4[m]-m_)*inv*gbv[m] + btv[m] + __ldg(pe + t*H_ + h);
                embdst[t*H_ + h] = val[m];
            }
            float d[8];
            #pragma unroll
            for (int jj = 0; jj < 8; jj++) {
                float dv = 0.f;
                #pragma unroll
                for (int m = 0; m < 4; m++) dv += val[m] * sipw[jj][lane + 32*m];
                dv += __shfl_xor_sync(FULLMASK, dv, 2);
                dv += __shfl_xor_sync(FULLMASK, dv, 1);
                d[jj] = dv;
            }
            float v = bfly8(d, lane);
            if ((lane & 3) == 0) {
                int j = (lane >> 2) & 7;
                pjdst[t * 8 + j] = v + sipb[j];
            }
        }
    }
    __syncthreads();
    if (tid == 0) {
        sh_sc[0] = sh_redf[0][0] + sh_redf[1][0];
        sh_sc[1] = sh_redf[0][1] + sh_redf[1][1] + out_b[0];
    }
    __syncthreads();
    const float S1 = sh_sc[0], C0 = sh_sc[1];

    // virtual-permutation constants (F^4 = I)
    const int SM_[4][4] = {{8,12,14,3},{8,4,10,13},{8,12,6,7},{8,4,2,1}};
    const int C3M[4]    = {3,13,7,1};
    float stp[16];
    bool  c3b[4];
    #pragma unroll
    for (int k = 0; k < 4; k++) {
        #pragma unroll
        for (int q = 0; q < 4; q++) {
            float tq = sh_wct[gate][k][q];
            stp[k*4+q] = (__popc(lane & SM_[k][q]) & 1) ? tq : -tq;
        }
        c3b[k] = (__popc(lane & C3M[k]) & 1);
    }

    float h_c[2] = {0.f, 0.f}, c_c[2] = {0.f, 0.f};
    const float* embrow = g_emb + (size_t)e * T_ * H_;
    const float* pjrow  = g_pj  + (size_t)e * T_ * 8;

    // pj prefetch (4 publisher lanes per warp; plain loads: self-written data)
    const int pgrp = lane >> 3;
    const bool pjlane = ((lane & 7) == 0);
    float pj_carry = 0.f;
    if (pjlane) pj_carry = pjrow[w * 4 + pgrp];

    for (int t = 0; t < T_; t++) {
        float emb0 = embrow[t * H_ + tid];
        float emb1 = embrow[t * H_ + tid + 64];

        // ---- Phase B (R12 structure) ----
        {
            float d0 = 0.f, d1 = 0.f, d2 = 0.f, d3 = 0.f;
            #pragma unroll
            for (int i = 0; i < 4; i++) {
                float hv = sh_hs[lane + 32 * i];
                d0 += hv * wbr[0][i]; d1 += hv * wbr[1][i];
                d2 += hv * wbr[2][i]; d3 += hv * wbr[3][i];
            }
            d0 += __shfl_xor_sync(FULLMASK, d0, 16); d1 += __shfl_xor_sync(FULLMASK, d1, 16);
            d2 += __shfl_xor_sync(FULLMASK, d2, 16); d3 += __shfl_xor_sync(FULLMASK, d3, 16);
            d0 += __shfl_xor_sync(FULLMASK, d0, 8);  d1 += __shfl_xor_sync(FULLMASK, d1, 8);
            d2 += __shfl_xor_sync(FULLMASK, d2, 8);  d3 += __shfl_xor_sync(FULLMASK, d3, 8);
            float v = (pgrp == 0) ? d0 : (pgrp == 1) ? d1 : (pgrp == 2) ? d2 : d3;
            v += __shfl_xor_sync(FULLMASK, v, 4);
            v += __shfl_xor_sync(FULLMASK, v, 2);
            v += __shfl_xor_sync(FULLMASK, v, 1);
            if (pjlane) {
                ((float*)&sh_pj4[w])[pgrp] = v + pj_carry;
                int tn = (t < 127) ? t + 1 : 127;
                pj_carry = pjrow[tn * 8 + w * 4 + pgrp];
            }
        }
        __syncthreads();

        // ---- mini-LN(8) + angles (redundant per warp) ----
        float scl;
        float F0[8], F1[8];
        {
            int q = lane & 7;
            float pv = tanhff(((const float*)sh_pj4)[q]);
            float sm_ = pv, sq = pv*pv;
            sm_ += __shfl_xor_sync(FULLMASK, sm_, 1); sq += __shfl_xor_sync(FULLMASK, sq, 1);
            sm_ += __shfl_xor_sync(FULLMASK, sm_, 2); sq += __shfl_xor_sync(FULLMASK, sq, 2);
            sm_ += __shfl_xor_sync(FULLMASK, sm_, 4); sq += __shfl_xor_sync(FULLMASK, sq, 4);
            float mm = sm_ * 0.125f;
            float iv = rsqrtf(sq * 0.125f - mm*mm + EPS_);
            float a = 0.5f * ((pv - mm) * iv * sh_ing8[q] + sh_inb8[q]);
            float ss, cc; __sincosf(a, &ss, &cc);
            float tq = __fdividef(ss, cc);
            cc *= __shfl_xor_sync(FULLMASK, cc, 1);
            cc *= __shfl_xor_sync(FULLMASK, cc, 2);
            cc *= __shfl_xor_sync(FULLMASK, cc, 4);
            float cin = cc * 0.0625f;
            scl = cin * cin * cw2g;
            int base = lane & 24;
            #pragma unroll
            for (int q2 = 0; q2 < 8; q2++) {
                float tg = __shfl_sync(FULLMASK, tq, base | q2);
                F0[q2] = 1.f - tg; F1[q2] = 1.f + tg;
            }
        }

        // ---- Phase C: VQC (tan-form, virtual perm, f32x2) ----
        float2 st2[8];
        {
            float v0 = ((ll&8)?F1[0]:F0[0]) * ((ll&4)?F1[1]:F0[1])
                     * ((ll&2)?F1[2]:F0[2]) * ((ll&1)?F1[3]:F0[3]);
            float a0 = v0 * F0[4], a8 = v0 * F1[4];
            float b0 = a0*F0[5], b4 = a0*F1[5], b8 = a8*F0[5], b12 = a8*F1[5];
            float c0=b0*F0[6], c2=b0*F1[6], c4=b4*F0[6], c6=b4*F1[6];
            float c8=b8*F0[6], c10=b8*F1[6], c12=b12*F0[6], c14=b12*F1[6];
            st2[0]=make_float2(c0*F0[7],  c0*F1[7]);  st2[1]=make_float2(c2*F0[7],  c2*F1[7]);
            st2[2]=make_float2(c4*F0[7],  c4*F1[7]);  st2[3]=make_float2(c6*F0[7],  c6*F1[7]);
            st2[4]=make_float2(c8*F0[7],  c8*F1[7]);  st2[5]=make_float2(c10*F0[7], c10*F1[7]);
            st2[6]=make_float2(c12*F0[7], c12*F1[7]); st2[7]=make_float2(c14*F0[7], c14*F1[7]);
        }

        const int BM[4][4] = {{12,7,3,1},{11,5,2,1},{14,6,3,1},{8,4,2,1}};
        #pragma unroll
        for (int lyr = 0; lyr < 4; lyr++) {
            // c4
            { float2 tp = st2[4]; st2[4] = st2[6]; st2[6] = tp;
              tp = st2[5]; st2[5] = st2[7]; st2[7] = tp; }
            // c6
            { float tp;
              tp = st2[1].x; st2[1].x = st2[1].y; st2[1].y = tp;
              tp = st2[3].x; st2[3].x = st2[3].y; st2[3].y = tp;
              tp = st2[5].x; st2[5].x = st2[5].y; st2[5].y = tp;
              tp = st2[7].x; st2[7].x = st2[7].y; st2[7].y = tp; }
            // c5
            { float2 tp = st2[2]; st2[2] = st2[3]; st2[3] = tp;
              tp = st2[6]; st2[6] = st2[7]; st2[7] = tp; }
            // c3 (virtual-layout parity control)
            {
                bool cc3 = c3b[lyr];
                #pragma unroll
                for (int j = 0; j < 4; j++) {
                    float2 a = st2[j], b = st2[j+4];
                    st2[j].x   = cc3 ? b.x : a.x;  st2[j].y   = cc3 ? b.y : a.y;
                    st2[j+4].x = cc3 ? a.x : b.x;  st2[j+4].y = cc3 ? a.y : b.y;
                }
            }
            // lane-qubit RYs q0..q3
            #pragma unroll
            for (int q = 0; q < 4; q++) {
                const int bm = BM[lyr][q];
                float tq = stp[lyr*4+q];
                #pragma unroll
                for (int j = 0; j < 8; j++) {
                    float ox = __shfl_xor_sync(FULLMASK, st2[j].x, bm);
                    float oy = __shfl_xor_sync(FULLMASK, st2[j].y, bm);
                    st2[j].x = fmaf(tq, ox, st2[j].x);
                    st2[j].y = fmaf(tq, oy, st2[j].y);
                }
            }
            // reg-qubit RYs q4..q7 (f32x2 for q4,q5,q6)
            const float4 tl = *(const float4*)&sh_wct[gate][lyr][4];
            {
                float2 nt = make_float2(-tl.x, -tl.x), pt = make_float2(tl.x, tl.x);
                #pragma unroll
                for (int j = 0; j < 4; j++) {
                    float2 lo = st2[j], hi = st2[j+4];
                    st2[j]   = ffma2(nt, hi, lo);
                    st2[j+4] = ffma2(pt, lo, hi);
                }
            }
            {
                float2 nt = make_float2(-tl.y, -tl.y), pt = make_float2(tl.y, tl.y);
                #pragma unroll
                for (int j = 0; j < 8; j++) if (!(j & 2)) {
                    float2 lo = st2[j], hi = st2[j+2];
                    st2[j]   = ffma2(nt, hi, lo);
                    st2[j+2] = ffma2(pt, lo, hi);
                }
            }
            {
                float2 nt = make_float2(-tl.z, -tl.z), pt = make_float2(tl.z, tl.z);
                #pragma unroll
                for (int j = 0; j < 8; j += 2) {
                    float2 lo = st2[j], hi = st2[j+1];
                    st2[j]   = ffma2(nt, hi, lo);
                    st2[j+1] = ffma2(pt, lo, hi);
                }
            }
            {
                float tq = tl.w;
                #pragma unroll
                for (int j = 0; j < 8; j++) {
                    float a0 = st2[j].x, a1 = st2[j].y;
                    st2[j].x = fmaf(-tq, a1, a0);
                    st2[j].y = fmaf( tq, a0, a1);
                }
            }
        }

        // ---- measurement ----
        {
            float2 p2[8];
            #pragma unroll
            for (int j = 0; j < 8; j++) p2[j] = fmul2(st2[j], st2[j]);
            float s8[8], s4[4], s2[2];
            float z7=0, z6=0, z5=0;
            #pragma unroll
            for (int k = 0; k < 8; k++) { s8[k] = p2[k].x + p2[k].y; z7 += p2[k].x - p2[k].y; }
            #pragma unroll
            for (int k = 0; k < 4; k++) { s4[k] = s8[2*k]+s8[2*k+1]; z6 += s8[2*k]-s8[2*k+1]; }
            #pragma unroll
            for (int k = 0; k < 2; k++) { s2[k] = s4[2*k]+s4[2*k+1]; z5 += s4[2*k]-s4[2*k+1]; }
            float z4 = s2[0]-s2[1], Tt = s2[0]+s2[1];
            float o, z0v, z1v, z2v, z3v;

            o = __shfl_xor_sync(FULLMASK, Tt, 1);
            z3v = (lane & 1) ? (o - Tt) : (Tt - o); Tt += o;
            z4 += __shfl_xor_sync(FULLMASK, z4, 1);
            z5 += __shfl_xor_sync(FULLMASK, z5, 1);
            z6 += __shfl_xor_sync(FULLMASK, z6, 1);
            z7 += __shfl_xor_sync(FULLMASK, z7, 1);

            o = __shfl_xor_sync(FULLMASK, Tt, 2);
            z2v = (lane & 2) ? (o - Tt) : (Tt - o); Tt += o;
            z3v += __shfl_xor_sync(FULLMASK, z3v, 2);
            z4 += __shfl_xor_sync(FULLMASK, z4, 2);
            z5 += __shfl_xor_sync(FULLMASK, z5, 2);
            z6 += __shfl_xor_sync(FULLMASK, z6, 2);
            z7 += __shfl_xor_sync(FULLMASK, z7, 2);

            o = __shfl_xor_sync(FULLMASK, Tt, 4);
            z1v = (lane & 4) ? (o - Tt) : (Tt - o); Tt += o;
            z2v += __shfl_xor_sync(FULLMASK, z2v, 4);
            z3v += __shfl_xor_sync(FULLMASK, z3v, 4);
            z4 += __shfl_xor_sync(FULLMASK, z4, 4);
            z5 += __shfl_xor_sync(FULLMASK, z5, 4);
            z6 += __shfl_xor_sync(FULLMASK, z6, 4);
            z7 += __shfl_xor_sync(FULLMASK, z7, 4);

            o = __shfl_xor_sync(FULLMASK, Tt, 8);
            z0v = (lane & 8) ? (o - Tt) : (Tt - o);
            z1v += __shfl_xor_sync(FULLMASK, z1v, 8);
            z2v += __shfl_xor_sync(FULLMASK, z2v, 8);
            z3v += __shfl_xor_sync(FULLMASK, z3v, 8);
            z4 += __shfl_xor_sync(FULLMASK, z4, 8);
            z5 += __shfl_xor_sync(FULLMASK, z5, 8);
            z6 += __shfl_xor_sync(FULLMASK, z6, 8);
            z7 += __shfl_xor_sync(FULLMASK, z7, 8);

            if (ll == 0) {
                sh_z[gate][0] = make_float4(z0v*scl, z1v*scl, z2v*scl, z3v*scl);
                sh_z[gate][1] = make_float4(z4*scl, z5*scl, z6*scl, z7*scl);
            }
        }
        __syncthreads();

        // ---- Phase D ----
        {
            float4 zr[4][2];
            #pragma unroll
            for (int g = 0; g < 4; g++) { zr[g][0] = sh_z[g][0]; zr[g][1] = sh_z[g][1]; }
            float v[2];
            #pragma unroll
            for (int hh = 0; hh < 2; hh++) {
                float pre[4];
                #pragma unroll
                for (int g = 0; g < 4; g++) {
                    float4 z0 = zr[g][0], z1 = zr[g][1];
                    const float* pw = &pwr[hh][g*8];
                    pre[g] = bia[hh][g]
                           + z0.x*pw[0] + z0.y*pw[1] + z0.z*pw[2] + z0.w*pw[3]
                           + z1.x*pw[4] + z1.y*pw[5] + z1.z*pw[6] + z1.w*pw[7];
                }
                float i_t = sigf(pre[0]);
                float f_t = sigf(pre[1]);
                float g_t = tanhff(pre[2]);
                float o_t = sigf(pre[3]);
                c_c[hh] = f_t*c_c[hh] + i_t*g_t;
                h_c[hh] = o_t*tanhff(c_c[hh]);
                v[hh] = h_c[hh] + (hh ? emb1 : emb0);
            }
            sh_hs[tid] = h_c[0]; sh_hs[tid + 64] = h_c[1];
            float r0 = v[0] + v[1];
            float r1 = v[0]*v[0] + v[1]*v[1];
            float r2 = v[0]*gw0 + v[1]*gw1;
            r0 += __shfl_xor_sync(FULLMASK, r0, 16);
            r1 += __shfl_xor_sync(FULLMASK, r1, 16);
            r2 += __shfl_xor_sync(FULLMASK, r2, 16);
            r0 += __shfl_xor_sync(FULLMASK, r0, 8);
            r1 += __shfl_xor_sync(FULLMASK, r1, 8);
            r2 += __shfl_xor_sync(FULLMASK, r2, 8);
            float vv = (pgrp == 0) ? r0 : (pgrp == 1) ? r1 : r2;
            vv += __shfl_xor_sync(FULLMASK, vv, 4);
            vv += __shfl_xor_sync(FULLMASK, vv, 2);
            vv += __shfl_xor_sync(FULLMASK, vv, 1);
            if (pjlane && pgrp < 3) sh_redf[w][pgrp] = vv;
        }
        __syncthreads();
        if (tid == 0) {
            float Sv = sh_redf[0][0] + sh_redf[1][0];
            float Sq = sh_redf[0][1] + sh_redf[1][1];
            float Sg = sh_redf[0][2] + sh_redf[1][2];
            float m2 = Sv * (1.f/128.f);
            float inv2 = rsqrtf(Sq * (1.f/128.f) - m2*m2 + EPS_);
            out[(size_t)e * T_ + t] = inv2 * (Sg - m2 * S1) + C0;
        }
    }
}

extern "C" void kernel_launch(void* const* d_in, const int* in_sizes, int n_in,
                              void* d_out, int out_size) {
    const float* p[26];
    for (int i = 0; i < 26; i++) p[i] = (const float*)d_in[i];
    qlstm_kernel<<<1024, 64>>>(
        p[0], p[1], p[2], p[3], p[4], p[5], p[6], p[7], p[8], p[9],
        p[10], p[11], p[12], p[13], p[14], p[15], p[16], p[17], p[18], p[19],
        p[20], p[21], p[22], p[23], p[24], p[25],
        (float*)d_out);
}

// round 15
// speedup vs baseline: 1.0621x; 1.0305x over previous
#include <cuda_runtime.h>
#include <cuda_bf16.h>
#include <math.h>

#define FULLMASK 0xffffffffu

constexpr int T_ = 128;
constexpr int H_ = 128;
constexpr float EPS_ = 1e-5f;

__device__ float g_emb[1024 * 128 * 128];
__device__ float g_pj[1024 * 128 * 8 + 8];   // +8 pad: t=127 prefetch overrun

__device__ __forceinline__ float warp_sum(float v) {
    v += __shfl_xor_sync(FULLMASK, v, 16);
    v += __shfl_xor_sync(FULLMASK, v, 8);
    v += __shfl_xor_sync(FULLMASK, v, 4);
    v += __shfl_xor_sync(FULLMASK, v, 2);
    v += __shfl_xor_sync(FULLMASK, v, 1);
    return v;
}
__device__ __forceinline__ float sigf(float x)  { return 1.f / (1.f + __expf(-x)); }
__device__ __forceinline__ float tanhff(float x){ return 1.f - 2.f / (1.f + __expf(2.f * x)); }

__device__ __forceinline__ float2 ffma2(float2 a, float2 b, float2 c) {
    float2 d;
    asm("fma.rn.f32x2 %0, %1, %2, %3;"
        : "=l"(reinterpret_cast<unsigned long long&>(d))
        : "l"(reinterpret_cast<unsigned long long&>(a)),
          "l"(reinterpret_cast<unsigned long long&>(b)),
          "l"(reinterpret_cast<unsigned long long&>(c)));
    return d;
}
__device__ __forceinline__ float2 fmul2(float2 a, float2 b) {
    float2 d;
    asm("mul.rn.f32x2 %0, %1, %2;"
        : "=l"(reinterpret_cast<unsigned long long&>(d))
        : "l"(reinterpret_cast<unsigned long long&>(a)),
          "l"(reinterpret_cast<unsigned long long&>(b)));
    return d;
}

// ---------------- kernel 1: fused embeddings + emb-half proj dot ----------------
// grid 2048: CTA (e, half) handles t in [64*half, 64*half+64)
__global__ __launch_bounds__(128)
void emb_pj_kernel(const float* __restrict__ x, const float* __restrict__ pe,
                   const float* __restrict__ emb_w, const float* __restrict__ emb_b,
                   const float* __restrict__ emb_g, const float* __restrict__ emb_bt,
                   const float* __restrict__ ip_w,  const float* __restrict__ ip_b)
{
    const int e = blockIdx.x >> 1, half = blockIdx.x & 1;
    const int tid = threadIdx.x, w = tid >> 5, lane = tid & 31;
    __shared__ __align__(16) float sx[64 * 8];
    __shared__ __align__(16) float sipw[8][128];
    __shared__ float sipb[8];

    const float4* xg = (const float4*)(x + (size_t)e * 1024 + half * 512);
    ((float4*)sx)[tid] = xg[tid];
    #pragma unroll
    for (int i = tid; i < 1024; i += 128)
        sipw[i >> 7][i & 127] = ip_w[(i >> 7) * 256 + (i & 127)];
    if (tid < 8) sipb[tid] = ip_b[tid];

    float ew[4][8], gb[4], bt[4], bb[4];
    #pragma unroll
    for (int m = 0; m < 4; m++) {
        int h = lane + 32 * m;
        #pragma unroll
        for (int k = 0; k < 8; k++) ew[m][k] = emb_w[h * 8 + k];
        gb[m] = emb_g[h]; bt[m] = emb_bt[h]; bb[m] = emb_b[h];
    }
    __syncthreads();
    for (int it = 0; it < 16; it++) {
        int tl = it * 4 + w;            // local t within half
        int t  = half * 64 + tl;        // global t
        const float* xr = sx + tl * 8;
        float e4[4];
        #pragma unroll
        for (int m = 0; m < 4; m++) {
            float s = bb[m];
            #pragma unroll
            for (int k = 0; k < 8; k++) s += xr[k] * ew[m][k];
            e4[m] = s;
        }
        float s = (e4[0]+e4[1])+(e4[2]+e4[3]);
        float q = (e4[0]*e4[0]+e4[1]*e4[1])+(e4[2]*e4[2]+e4[3]*e4[3]);
        s += __shfl_xor_sync(FULLMASK, s, 16);
        q += __shfl_xor_sync(FULLMASK, q, 16);
        float u = (lane & 16) ? q : s;
        u += __shfl_xor_sync(FULLMASK, u, 8);
        u += __shfl_xor_sync(FULLMASK, u, 4);
        u += __shfl_xor_sync(FULLMASK, u, 2);
        u += __shfl_xor_sync(FULLMASK, u, 1);
        float other = __shfl_xor_sync(FULLMASK, u, 16);
        float sf = (lane & 16) ? other : u;
        float qf = (lane & 16) ? u : other;
        float m_ = sf * (1.f/128.f);
        float inv = rsqrtf(qf * (1.f/128.f) - m_*m_ + EPS_);
        float val[4];
        #pragma unroll
        for (int m = 0; m < 4; m++) {
            int h = lane + 32 * m;
            val[m] = (e4[m]-m_)*inv*gb[m] + bt[m] + __ldg(pe + t*H_ + h);
            g_emb[(size_t)e*T_*H_ + t*H_ + h] = val[m];
        }
        float d[8];
        #pragma unroll
        for (int jj = 0; jj < 8; jj++) {
            float dv = 0.f;
            #pragma unroll
            for (int m = 0; m < 4; m++) dv += val[m] * sipw[jj][lane + 32*m];
            d[jj] = dv;
        }
        #pragma unroll
        for (int jj = 0; jj < 8; jj++) {
            d[jj] += __shfl_xor_sync(FULLMASK, d[jj], 16);
            d[jj] += __shfl_xor_sync(FULLMASK, d[jj], 8);
        }
        int g8 = lane >> 3;
        float vA = (g8 & 2) ? ((g8 & 1) ? d[3] : d[2]) : ((g8 & 1) ? d[1] : d[0]);
        float vB = (g8 & 2) ? ((g8 & 1) ? d[7] : d[6]) : ((g8 & 1) ? d[5] : d[4]);
        vA += __shfl_xor_sync(FULLMASK, vA, 4);
        vB += __shfl_xor_sync(FULLMASK, vB, 4);
        vA += __shfl_xor_sync(FULLMASK, vA, 2);
        vB += __shfl_xor_sync(FULLMASK, vB, 2);
        vA += __shfl_xor_sync(FULLMASK, vA, 1);
        vB += __shfl_xor_sync(FULLMASK, vB, 1);
        if ((lane & 7) == 0) {
            float* gp = g_pj + ((size_t)e*T_ + t) * 8;
            gp[g8]     = vA + sipb[g8];
            gp[g8 + 4] = vB + sipb[g8 + 4];
        }
    }
}

// ---------------- kernel 2: recurrence (R12 structure, verbatim hot loop) ----------------
__global__ __launch_bounds__(64, 7)
void qlstm_kernel(
    const float* __restrict__ ip_w,
    const float* __restrict__ in_g,  const float* __restrict__ in_b,
    const float* __restrict__ wq_i,  const float* __restrict__ wq_f,
    const float* __restrict__ wq_g,  const float* __restrict__ wq_o,
    const float* __restrict__ pi_w,  const float* __restrict__ pi_b,
    const float* __restrict__ pf_w,  const float* __restrict__ pf_b,
    const float* __restrict__ pg_w,  const float* __restrict__ pg_b,
    const float* __restrict__ po_w,  const float* __restrict__ po_b,
    const float* __restrict__ on_g,  const float* __restrict__ on_b,
    const float* __restrict__ out_w, const float* __restrict__ out_b,
    float* __restrict__ out)
{
    const int e = blockIdx.x;
    const int tid = threadIdx.x, w = tid >> 5, lane = tid & 31;
    const int ll = lane & 15;
    const int gate = 2 * w + (lane >> 4);

    __shared__ __align__(16) float  sh_hs[128];
    __shared__ __align__(16) float  sh_wct[4][4][8];
    __shared__ __align__(16) float4 sh_pj4[2];
    __shared__ __align__(16) float4 sh_z[4][2];
    __shared__ float sh_redf[2][4];
    __shared__ float sh_sc[2], sh_ing8[8], sh_inb8[8];

    {
        const float* wqp[4] = {wq_i, wq_f, wq_g, wq_o};
        #pragma unroll
        for (int i = tid; i < 128; i += 64) {
            int g = i >> 5, rem = i & 31, lyr = rem >> 3, q = rem & 7;
            sh_wct[g][lyr][q] = tanf(0.5f * wqp[g][lyr * 8 + q]);
        }
        if (tid < 8) { sh_ing8[tid] = in_g[tid]; sh_inb8[tid] = in_b[tid]; }
    }
    float cw2g;
    {
        const float* wqp[4] = {wq_i, wq_f, wq_g, wq_o};
        float cw = 1.f;
        #pragma unroll
        for (int k = 0; k < 32; k++) cw *= cosf(0.5f * wqp[gate][k]);
        cw2g = cw * cw;
    }

    float wbr[4][4];
    #pragma unroll
    for (int jj = 0; jj < 4; jj++)
        #pragma unroll
        for (int i = 0; i < 4; i++)
            wbr[jj][i] = ip_w[(4*w + jj) * 256 + 128 + lane + 32*i];

    float pwr[2][32];
    float bia[2][4];
    {
        const float* pw[4] = {pi_w, pf_w, pg_w, po_w};
        const float* pb[4] = {pi_b, pf_b, pg_b, po_b};
        #pragma unroll
        for (int hh = 0; hh < 2; hh++) {
            int h = tid + 64 * hh;
            #pragma unroll
            for (int g = 0; g < 4; g++) {
                bia[hh][g] = pb[g][h];
                #pragma unroll
                for (int q = 0; q < 8; q++) pwr[hh][g*8+q] = pw[g][h*8+q];
            }
        }
    }
    float gw0 = on_g[tid]*out_w[tid],       gw1 = on_g[tid+64]*out_w[tid+64];
    float bw0 = on_b[tid]*out_w[tid],       bw1 = on_b[tid+64]*out_w[tid+64];
    {
        float s1 = warp_sum(gw0 + gw1), s2 = warp_sum(bw0 + bw1);
        if (lane == 0) { sh_redf[w][0] = s1; sh_redf[w][1] = s2; }
    }
    sh_hs[tid] = 0.f; sh_hs[tid + 64] = 0.f;
    __syncthreads();
    if (tid == 0) {
        sh_sc[0] = sh_redf[0][0] + sh_redf[1][0];
        sh_sc[1] = sh_redf[0][1] + sh_redf[1][1] + out_b[0];
    }
    __syncthreads();
    const float S1 = sh_sc[0], C0 = sh_sc[1];

    // virtual-permutation constants (F^4 = I)
    const int SM_[4][4] = {{8,12,14,3},{8,4,10,13},{8,12,6,7},{8,4,2,1}};
    const int C3M[4]    = {3,13,7,1};
    float stp[16];
    bool  c3b[4];
    #pragma unroll
    for (int k = 0; k < 4; k++) {
        #pragma unroll
        for (int q = 0; q < 4; q++) {
            float tq = sh_wct[gate][k][q];
            stp[k*4+q] = (__popc(lane & SM_[k][q]) & 1) ? tq : -tq;
        }
        c3b[k] = (__popc(lane & C3M[k]) & 1);
    }

    float h_c[2] = {0.f, 0.f}, c_c[2] = {0.f, 0.f};
    const float* embrow = g_emb + (size_t)e * T_ * H_;
    const float* pjp    = g_pj  + (size_t)e * T_ * 8;

    const int pgrp = lane >> 3;
    const bool pjlane = ((lane & 7) == 0);
    float pj_carry = 0.f;
    if (pjlane) pj_carry = pjp[w * 4 + pgrp];

    for (int t = 0; t < T_; t++) {
        float emb0 = __ldg(embrow + t * H_ + tid);
        float emb1 = __ldg(embrow + t * H_ + tid + 64);

        // ---- Phase B ----
        {
            float d0 = 0.f, d1 = 0.f, d2 = 0.f, d3 = 0.f;
            #pragma unroll
            for (int i = 0; i < 4; i++) {
                float hv = sh_hs[lane + 32 * i];
                d0 += hv * wbr[0][i]; d1 += hv * wbr[1][i];
                d2 += hv * wbr[2][i]; d3 += hv * wbr[3][i];
            }
            d0 += __shfl_xor_sync(FULLMASK, d0, 16); d1 += __shfl_xor_sync(FULLMASK, d1, 16);
            d2 += __shfl_xor_sync(FULLMASK, d2, 16); d3 += __shfl_xor_sync(FULLMASK, d3, 16);
            d0 += __shfl_xor_sync(FULLMASK, d0, 8);  d1 += __shfl_xor_sync(FULLMASK, d1, 8);
            d2 += __shfl_xor_sync(FULLMASK, d2, 8);  d3 += __shfl_xor_sync(FULLMASK, d3, 8);
            float v = (pgrp == 0) ? d0 : (pgrp == 1) ? d1 : (pgrp == 2) ? d2 : d3;
            v += __shfl_xor_sync(FULLMASK, v, 4);
            v += __shfl_xor_sync(FULLMASK, v, 2);
            v += __shfl_xor_sync(FULLMASK, v, 1);
            if (pjlane) {
                ((float*)&sh_pj4[w])[pgrp] = v + pj_carry;
                pj_carry = pjp[(t + 1) * 8 + w * 4 + pgrp];   // pad-safe overrun at t=127
            }
        }
        __syncthreads();

        // ---- mini-LN(8) + angles (redundant per warp) ----
        float scl;
        float F0[8], F1[8];
        {
            int q = lane & 7;
            float pv = tanhff(((const float*)sh_pj4)[q]);
            float sm_ = pv, sq = pv*pv;
            sm_ += __shfl_xor_sync(FULLMASK, sm_, 1); sq += __shfl_xor_sync(FULLMASK, sq, 1);
            sm_ += __shfl_xor_sync(FULLMASK, sm_, 2); sq += __shfl_xor_sync(FULLMASK, sq, 2);
            sm_ += __shfl_xor_sync(FULLMASK, sm_, 4); sq += __shfl_xor_sync(FULLMASK, sq, 4);
            float mm = sm_ * 0.125f;
            float iv = rsqrtf(sq * 0.125f - mm*mm + EPS_);
            float a = 0.5f * ((pv - mm) * iv * sh_ing8[q] + sh_inb8[q]);
            float ss, cc; __sincosf(a, &ss, &cc);
            float tq = __fdividef(ss, cc);
            cc *= __shfl_xor_sync(FULLMASK, cc, 1);
            cc *= __shfl_xor_sync(FULLMASK, cc, 2);
            cc *= __shfl_xor_sync(FULLMASK, cc, 4);
            float cin = cc * 0.0625f;
            scl = cin * cin * cw2g;
            int base = lane & 24;
            #pragma unroll
            for (int q2 = 0; q2 < 8; q2++) {
                float tg = __shfl_sync(FULLMASK, tq, base | q2);
                F0[q2] = 1.f - tg; F1[q2] = 1.f + tg;
            }
        }

        // ---- Phase C: VQC (tan-form, virtual perm, f32x2) ----
        float2 st2[8];
        {
            float v0 = ((ll&8)?F1[0]:F0[0]) * ((ll&4)?F1[1]:F0[1])
                     * ((ll&2)?F1[2]:F0[2]) * ((ll&1)?F1[3]:F0[3]);
            float a0 = v0 * F0[4], a8 = v0 * F1[4];
            float b0 = a0*F0[5], b4 = a0*F1[5], b8 = a8*F0[5], b12 = a8*F1[5];
            float c0=b0*F0[6], c2=b0*F1[6], c4=b4*F0[6], c6=b4*F1[6];
            float c8=b8*F0[6], c10=b8*F1[6], c12=b12*F0[6], c14=b12*F1[6];
            st2[0]=make_float2(c0*F0[7],  c0*F1[7]);  st2[1]=make_float2(c2*F0[7],  c2*F1[7]);
            st2[2]=make_float2(c4*F0[7],  c4*F1[7]);  st2[3]=make_float2(c6*F0[7],  c6*F1[7]);
            st2[4]=make_float2(c8*F0[7],  c8*F1[7]);  st2[5]=make_float2(c10*F0[7], c10*F1[7]);
            st2[6]=make_float2(c12*F0[7], c12*F1[7]); st2[7]=make_float2(c14*F0[7], c14*F1[7]);
        }

        const int BM[4][4] = {{12,7,3,1},{11,5,2,1},{14,6,3,1},{8,4,2,1}};
        #pragma unroll
        for (int lyr = 0; lyr < 4; lyr++) {
            // c4
            { float2 tp = st2[4]; st2[4] = st2[6]; st2[6] = tp;
              tp = st2[5]; st2[5] = st2[7]; st2[7] = tp; }
            // c6
            { float tp;
              tp = st2[1].x; st2[1].x = st2[1].y; st2[1].y = tp;
              tp = st2[3].x; st2[3].x = st2[3].y; st2[3].y = tp;
              tp = st2[5].x; st2[5].x = st2[5].y; st2[5].y = tp;
              tp = st2[7].x; st2[7].x = st2[7].y; st2[7].y = tp; }
            // c5
            { float2 tp = st2[2]; st2[2] = st2[3]; st2[3] = tp;
              tp = st2[6]; st2[6] = st2[7]; st2[7] = tp; }
            // c3 (virtual-layout parity control)
            {
                bool cc3 = c3b[lyr];
                #pragma unroll
                for (int j = 0; j < 4; j++) {
                    float2 a = st2[j], b = st2[j+4];
                    st2[j].x   = cc3 ? b.x : a.x;  st2[j].y   = cc3 ? b.y : a.y;
                    st2[j+4].x = cc3 ? a.x : b.x;  st2[j+4].y = cc3 ? a.y : b.y;
                }
            }
            // lane-qubit RYs q0..q3
            #pragma unroll
            for (int q = 0; q < 4; q++) {
                const int bm = BM[lyr][q];
                float tq = stp[lyr*4+q];
                #pragma unroll
                for (int j = 0; j < 8; j++) {
                    float ox = __shfl_xor_sync(FULLMASK, st2[j].x, bm);
                    float oy = __shfl_xor_sync(FULLMASK, st2[j].y, bm);
                    st2[j].x = fmaf(tq, ox, st2[j].x);
                    st2[j].y = fmaf(tq, oy, st2[j].y);
                }
            }
            // reg-qubit RYs q4..q7 (f32x2 for q4,q5,q6)
            const float4 tl = *(const float4*)&sh_wct[gate][lyr][4];
            {
                float2 nt = make_float2(-tl.x, -tl.x), pt = make_float2(tl.x, tl.x);
                #pragma unroll
                for (int j = 0; j < 4; j++) {
                    float2 lo = st2[j], hi = st2[j+4];
                    st2[j]   = ffma2(nt, hi, lo);
                    st2[j+4] = ffma2(pt, lo, hi);
                }
            }
            {
                float2 nt = make_float2(-tl.y, -tl.y), pt = make_float2(tl.y, tl.y);
                #pragma unroll
                for (int j = 0; j < 8; j++) if (!(j & 2)) {
                    float2 lo = st2[j], hi = st2[j+2];
                    st2[j]   = ffma2(nt, hi, lo);
                    st2[j+2] = ffma2(pt, lo, hi);
                }
            }
            {
                float2 nt = make_float2(-tl.z, -tl.z), pt = make_float2(tl.z, tl.z);
                #pragma unroll
                for (int j = 0; j < 8; j += 2) {
                    float2 lo = st2[j], hi = st2[j+1];
                    st2[j]   = ffma2(nt, hi, lo);
                    st2[j+1] = ffma2(pt, lo, hi);
                }
            }
            {
                float tq = tl.w;
                #pragma unroll
                for (int j = 0; j < 8; j++) {
                    float a0 = st2[j].x, a1 = st2[j].y;
                    st2[j].x = fmaf(-tq, a1, a0);
                    st2[j].y = fmaf( tq, a0, a1);
                }
            }
        }

        // ---- measurement ----
        {
            float2 p2[8];
            #pragma unroll
            for (int j = 0; j < 8; j++) p2[j] = fmul2(st2[j], st2[j]);
            float s8[8], s4[4], s2[2];
            float z7=0, z6=0, z5=0;
            #pragma unroll
            for (int k = 0; k < 8; k++) { s8[k] = p2[k].x + p2[k].y; z7 += p2[k].x - p2[k].y; }
            #pragma unroll
            for (int k = 0; k < 4; k++) { s4[k] = s8[2*k]+s8[2*k+1]; z6 += s8[2*k]-s8[2*k+1]; }
            #pragma unroll
            for (int k = 0; k < 2; k++) { s2[k] = s4[2*k]+s4[2*k+1]; z5 += s4[2*k]-s4[2*k+1]; }
            float z4 = s2[0]-s2[1], Tt = s2[0]+s2[1];
            float o, z0v, z1v, z2v, z3v;

            o = __shfl_xor_sync(FULLMASK, Tt, 1);
            z3v = (lane & 1) ? (o - Tt) : (Tt - o); Tt += o;
            z4 += __shfl_xor_sync(FULLMASK, z4, 1);
            z5 += __shfl_xor_sync(FULLMASK, z5, 1);
            z6 += __shfl_xor_sync(FULLMASK, z6, 1);
            z7 += __shfl_xor_sync(FULLMASK, z7, 1);

            o = __shfl_xor_sync(FULLMASK, Tt, 2);
            z2v = (lane & 2) ? (o - Tt) : (Tt - o); Tt += o;
            z3v += __shfl_xor_sync(FULLMASK, z3v, 2);
            z4 += __shfl_xor_sync(FULLMASK, z4, 2);
            z5 += __shfl_xor_sync(FULLMASK, z5, 2);
            z6 += __shfl_xor_sync(FULLMASK, z6, 2);
            z7 += __shfl_xor_sync(FULLMASK, z7, 2);

            o = __shfl_xor_sync(FULLMASK, Tt, 4);
            z1v = (lane & 4) ? (o - Tt) : (Tt - o); Tt += o;
            z2v += __shfl_xor_sync(FULLMASK, z2v, 4);
            z3v += __shfl_xor_sync(FULLMASK, z3v, 4);
            z4 += __shfl_xor_sync(FULLMASK, z4, 4);
            z5 += __shfl_xor_sync(FULLMASK, z5, 4);
            z6 += __shfl_xor_sync(FULLMASK, z6, 4);
            z7 += __shfl_xor_sync(FULLMASK, z7, 4);

            o = __shfl_xor_sync(FULLMASK, Tt, 8);
            z0v = (lane & 8) ? (o - Tt) : (Tt - o);
            z1v += __shfl_xor_sync(FULLMASK, z1v, 8);
            z2v += __shfl_xor_sync(FULLMASK, z2v, 8);
            z3v += __shfl_xor_sync(FULLMASK, z3v, 8);
            z4 += __shfl_xor_sync(FULLMASK, z4, 8);
            z5 += __shfl_xor_sync(FULLMASK, z5, 8);
            z6 += __shfl_xor_sync(FULLMASK, z6, 8);
            z7 += __shfl_xor_sync(FULLMASK, z7, 8);

            if (ll == 0) {
                sh_z[gate][0] = make_float4(z0v*scl, z1v*scl, z2v*scl, z3v*scl);
                sh_z[gate][1] = make_float4(z4*scl, z5*scl, z6*scl, z7*scl);
            }
        }
        __syncthreads();

        // ---- Phase D ----
        {
            float4 zr[4][2];
            #pragma unroll
            for (int g = 0; g < 4; g++) { zr[g][0] = sh_z[g][0]; zr[g][1] = sh_z[g][1]; }
            float v[2];
            #pragma unroll
            for (int hh = 0; hh < 2; hh++) {
                float pre[4];
                #pragma unroll
                for (int g = 0; g < 4; g++) {
                    float4 z0 = zr[g][0], z1 = zr[g][1];
                    const float* pw = &pwr[hh][g*8];
                    pre[g] = bia[hh][g]
                           + z0.x*pw[0] + z0.y*pw[1] + z0.z*pw[2] + z0.w*pw[3]
                           + z1.x*pw[4] + z1.y*pw[5] + z1.z*pw[6] + z1.w*pw[7];
                }
                float i_t = sigf(pre[0]);
                float f_t = sigf(pre[1]);
                float g_t = tanhff(pre[2]);
                float o_t = sigf(pre[3]);
                c_c[hh] = f_t*c_c[hh] + i_t*g_t;
                h_c[hh] = o_t*tanhff(c_c[hh]);
                v[hh] = h_c[hh] + (hh ? emb1 : emb0);
            }
            sh_hs[tid] = h_c[0]; sh_hs[tid + 64] = h_c[1];
            float r0 = v[0] + v[1];
            float r1 = v[0]*v[0] + v[1]*v[1];
            float r2 = v[0]*gw0 + v[1]*gw1;
            r0 += __shfl_xor_sync(FULLMASK, r0, 16);
            r1 += __shfl_xor_sync(FULLMASK, r1, 16);
            r2 += __shfl_xor_sync(FULLMASK, r2, 16);
            r0 += __shfl_xor_sync(FULLMASK, r0, 8);
            r1 += __shfl_xor_sync(FULLMASK, r1, 8);
            r2 += __shfl_xor_sync(FULLMASK, r2, 8);
            float vv = (pgrp == 0) ? r0 : (pgrp == 1) ? r1 : r2;
            vv += __shfl_xor_sync(FULLMASK, vv, 4);
            vv += __shfl_xor_sync(FULLMASK, vv, 2);
            vv += __shfl_xor_sync(FULLMASK, vv, 1);
            if (pjlane && pgrp < 3) sh_redf[w][pgrp] = vv;
        }
        __syncthreads();
        if (tid == 0) {
            float Sv = sh_redf[0][0] + sh_redf[1][0];
            float Sq = sh_redf[0][1] + sh_redf[1][1];
            float Sg = sh_redf[0][2] + sh_redf[1][2];
            float m2 = Sv * (1.f/128.f);
            float inv2 = rsqrtf(Sq * (1.f/128.f) - m2*m2 + EPS_);
            out[(size_t)e * T_ + t] = inv2 * (Sg - m2 * S1) + C0;
        }
    }
}

extern "C" void kernel_launch(void* const* d_in, const int* in_sizes, int n_in,
                              void* d_out, int out_size) {
    const float* p[26];
    for (int i = 0; i < 26; i++) p[i] = (const float*)d_in[i];
    emb_pj_kernel<<<2048, 128>>>(p[0], p[1], p[2], p[3], p[4], p[5], p[6], p[7]);
    qlstm_kernel<<<1024, 64>>>(
        p[6], p[8], p[9], p[10], p[11], p[12], p[13],
        p[14], p[15], p[16], p[17], p[18], p[19], p[20], p[21],
        p[22], p[23], p[24], p[25], (float*)d_out);
}

// round 16
// speedup vs baseline: 1.0760x; 1.0130x over previous
#include <cuda_runtime.h>
#include <cuda_bf16.h>
#include <math.h>

#define FULLMASK 0xffffffffu

constexpr int T_ = 128;
constexpr int H_ = 128;
constexpr float EPS_ = 1e-5f;

__device__ float g_emb[1024 * 128 * 128];
__device__ float g_pj[1024 * 128 * 8 + 8];   // +8 pad: t=127 prefetch overrun

__device__ __forceinline__ float warp_sum(float v) {
    v += __shfl_xor_sync(FULLMASK, v, 16);
    v += __shfl_xor_sync(FULLMASK, v, 8);
    v += __shfl_xor_sync(FULLMASK, v, 4);
    v += __shfl_xor_sync(FULLMASK, v, 2);
    v += __shfl_xor_sync(FULLMASK, v, 1);
    return v;
}
__device__ __forceinline__ float sigf(float x)  { return 1.f / (1.f + __expf(-x)); }
__device__ __forceinline__ float tanhff(float x){ return 1.f - 2.f / (1.f + __expf(2.f * x)); }

__device__ __forceinline__ float2 ffma2(float2 a, float2 b, float2 c) {
    float2 d;
    asm("fma.rn.f32x2 %0, %1, %2, %3;"
        : "=l"(reinterpret_cast<unsigned long long&>(d))
        : "l"(reinterpret_cast<unsigned long long&>(a)),
          "l"(reinterpret_cast<unsigned long long&>(b)),
          "l"(reinterpret_cast<unsigned long long&>(c)));
    return d;
}
__device__ __forceinline__ float2 fmul2(float2 a, float2 b) {
    float2 d;
    asm("mul.rn.f32x2 %0, %1, %2;"
        : "=l"(reinterpret_cast<unsigned long long&>(d))
        : "l"(reinterpret_cast<unsigned long long&>(a)),
          "l"(reinterpret_cast<unsigned long long&>(b)));
    return d;
}

// ---------------- kernel 1: fused embeddings + emb-half proj dot (R12: 1024 CTAs) ----------------
__global__ __launch_bounds__(128)
void emb_pj_kernel(const float* __restrict__ x, const float* __restrict__ pe,
                   const float* __restrict__ emb_w, const float* __restrict__ emb_b,
                   const float* __restrict__ emb_g, const float* __restrict__ emb_bt,
                   const float* __restrict__ ip_w,  const float* __restrict__ ip_b)
{
    const int e = blockIdx.x, tid = threadIdx.x, w = tid >> 5, lane = tid & 31;
    __shared__ __align__(16) float sx[T_ * 8];
    __shared__ __align__(16) float sipw[8][128];
    __shared__ float sipb[8];

    const float4* xg = (const float4*)(x + (size_t)e * T_ * 8);
    ((float4*)sx)[tid] = xg[tid];
    ((float4*)sx)[tid + 128] = xg[tid + 128];
    #pragma unroll
    for (int i = tid; i < 1024; i += 128)
        sipw[i >> 7][i & 127] = ip_w[(i >> 7) * 256 + (i & 127)];
    if (tid < 8) sipb[tid] = ip_b[tid];

    float ew[4][8], gb[4], bt[4], bb[4];
    #pragma unroll
    for (int m = 0; m < 4; m++) {
        int h = lane + 32 * m;
        #pragma unroll
        for (int k = 0; k < 8; k++) ew[m][k] = emb_w[h * 8 + k];
        gb[m] = emb_g[h]; bt[m] = emb_bt[h]; bb[m] = emb_b[h];
    }
    __syncthreads();
    for (int it = 0; it < 32; it++) {
        int t = it * 4 + w;
        const float* xr = sx + t * 8;
        float e4[4];
        #pragma unroll
        for (int m = 0; m < 4; m++) {
            float s = bb[m];
            #pragma unroll
            for (int k = 0; k < 8; k++) s += xr[k] * ew[m][k];
            e4[m] = s;
        }
        float s = (e4[0]+e4[1])+(e4[2]+e4[3]);
        float q = (e4[0]*e4[0]+e4[1]*e4[1])+(e4[2]*e4[2]+e4[3]*e4[3]);
        s += __shfl_xor_sync(FULLMASK, s, 16);
        q += __shfl_xor_sync(FULLMASK, q, 16);
        float u = (lane & 16) ? q : s;
        u += __shfl_xor_sync(FULLMASK, u, 8);
        u += __shfl_xor_sync(FULLMASK, u, 4);
        u += __shfl_xor_sync(FULLMASK, u, 2);
        u += __shfl_xor_sync(FULLMASK, u, 1);
        float other = __shfl_xor_sync(FULLMASK, u, 16);
        float sf = (lane & 16) ? other : u;
        float qf = (lane & 16) ? u : other;
        float m_ = sf * (1.f/128.f);
        float inv = rsqrtf(qf * (1.f/128.f) - m_*m_ + EPS_);
        float val[4];
        #pragma unroll
        for (int m = 0; m < 4; m++) {
            int h = lane + 32 * m;
            val[m] = (e4[m]-m_)*inv*gb[m] + bt[m] + __ldg(pe + t*H_ + h);
            g_emb[(size_t)e*T_*H_ + t*H_ + h] = val[m];
        }
        float d[8];
        #pragma unroll
        for (int jj = 0; jj < 8; jj++) {
            float dv = 0.f;
            #pragma unroll
            for (int m = 0; m < 4; m++) dv += val[m] * sipw[jj][lane + 32*m];
            d[jj] = dv;
        }
        #pragma unroll
        for (int jj = 0; jj < 8; jj++) {
            d[jj] += __shfl_xor_sync(FULLMASK, d[jj], 16);
            d[jj] += __shfl_xor_sync(FULLMASK, d[jj], 8);
        }
        int g8 = lane >> 3;
        float vA = (g8 & 2) ? ((g8 & 1) ? d[3] : d[2]) : ((g8 & 1) ? d[1] : d[0]);
        float vB = (g8 & 2) ? ((g8 & 1) ? d[7] : d[6]) : ((g8 & 1) ? d[5] : d[4]);
        vA += __shfl_xor_sync(FULLMASK, vA, 4);
        vB += __shfl_xor_sync(FULLMASK, vB, 4);
        vA += __shfl_xor_sync(FULLMASK, vA, 2);
        vB += __shfl_xor_sync(FULLMASK, vB, 2);
        vA += __shfl_xor_sync(FULLMASK, vA, 1);
        vB += __shfl_xor_sync(FULLMASK, vB, 1);
        if ((lane & 7) == 0) {
            float* gp = g_pj + ((size_t)e*T_ + t) * 8;
            gp[g8]     = vA + sipb[g8];
            gp[g8 + 4] = vB + sipb[g8 + 4];
        }
    }
}

// ---------------- kernel 2: recurrence (R15 main kernel, measured 599.4us) ----------------
__global__ __launch_bounds__(64, 7)
void qlstm_kernel(
    const float* __restrict__ ip_w,
    const float* __restrict__ in_g,  const float* __restrict__ in_b,
    const float* __restrict__ wq_i,  const float* __restrict__ wq_f,
    const float* __restrict__ wq_g,  const float* __restrict__ wq_o,
    const float* __restrict__ pi_w,  const float* __restrict__ pi_b,
    const float* __restrict__ pf_w,  const float* __restrict__ pf_b,
    const float* __restrict__ pg_w,  const float* __restrict__ pg_b,
    const float* __restrict__ po_w,  const float* __restrict__ po_b,
    const float* __restrict__ on_g,  const float* __restrict__ on_b,
    const float* __restrict__ out_w, const float* __restrict__ out_b,
    float* __restrict__ out)
{
    const int e = blockIdx.x;
    const int tid = threadIdx.x, w = tid >> 5, lane = tid & 31;
    const int ll = lane & 15;
    const int gate = 2 * w + (lane >> 4);

    __shared__ __align__(16) float  sh_hs[128];
    __shared__ __align__(16) float  sh_wct[4][4][8];
    __shared__ __align__(16) float4 sh_pj4[2];
    __shared__ __align__(16) float4 sh_z[4][2];
    __shared__ float sh_redf[2][4];
    __shared__ float sh_sc[2], sh_ing8[8], sh_inb8[8];

    {
        const float* wqp[4] = {wq_i, wq_f, wq_g, wq_o};
        #pragma unroll
        for (int i = tid; i < 128; i += 64) {
            int g = i >> 5, rem = i & 31, lyr = rem >> 3, q = rem & 7;
            sh_wct[g][lyr][q] = tanf(0.5f * wqp[g][lyr * 8 + q]);
        }
        if (tid < 8) { sh_ing8[tid] = in_g[tid]; sh_inb8[tid] = in_b[tid]; }
    }
    float cw2g;
    {
        const float* wqp[4] = {wq_i, wq_f, wq_g, wq_o};
        float cw = 1.f;
        #pragma unroll
        for (int k = 0; k < 32; k++) cw *= cosf(0.5f * wqp[gate][k]);
        cw2g = cw * cw;
    }

    float wbr[4][4];
    #pragma unroll
    for (int jj = 0; jj < 4; jj++)
        #pragma unroll
        for (int i = 0; i < 4; i++)
            wbr[jj][i] = ip_w[(4*w + jj) * 256 + 128 + lane + 32*i];

    float pwr[2][32];
    float bia[2][4];
    {
        const float* pw[4] = {pi_w, pf_w, pg_w, po_w};
        const float* pb[4] = {pi_b, pf_b, pg_b, po_b};
        #pragma unroll
        for (int hh = 0; hh < 2; hh++) {
            int h = tid + 64 * hh;
            #pragma unroll
            for (int g = 0; g < 4; g++) {
                bia[hh][g] = pb[g][h];
                #pragma unroll
                for (int q = 0; q < 8; q++) pwr[hh][g*8+q] = pw[g][h*8+q];
            }
        }
    }
    float gw0 = on_g[tid]*out_w[tid],       gw1 = on_g[tid+64]*out_w[tid+64];
    float bw0 = on_b[tid]*out_w[tid],       bw1 = on_b[tid+64]*out_w[tid+64];
    {
        float s1 = warp_sum(gw0 + gw1), s2 = warp_sum(bw0 + bw1);
        if (lane == 0) { sh_redf[w][0] = s1; sh_redf[w][1] = s2; }
    }
    sh_hs[tid] = 0.f; sh_hs[tid + 64] = 0.f;
    __syncthreads();
    if (tid == 0) {
        sh_sc[0] = sh_redf[0][0] + sh_redf[1][0];
        sh_sc[1] = sh_redf[0][1] + sh_redf[1][1] + out_b[0];
    }
    __syncthreads();
    const float S1 = sh_sc[0], C0 = sh_sc[1];

    // virtual-permutation constants (F^4 = I)
    const int SM_[4][4] = {{8,12,14,3},{8,4,10,13},{8,12,6,7},{8,4,2,1}};
    const int C3M[4]    = {3,13,7,1};
    float stp[16];
    bool  c3b[4];
    #pragma unroll
    for (int k = 0; k < 4; k++) {
        #pragma unroll
        for (int q = 0; q < 4; q++) {
            float tq = sh_wct[gate][k][q];
            stp[k*4+q] = (__popc(lane & SM_[k][q]) & 1) ? tq : -tq;
        }
        c3b[k] = (__popc(lane & C3M[k]) & 1);
    }

    float h_c[2] = {0.f, 0.f}, c_c[2] = {0.f, 0.f};
    const float* embrow = g_emb + (size_t)e * T_ * H_;
    const float* pjp    = g_pj  + (size_t)e * T_ * 8;

    const int pgrp = lane >> 3;
    const bool pjlane = ((lane & 7) == 0);
    float pj_carry = 0.f;
    if (pjlane) pj_carry = pjp[w * 4 + pgrp];

    for (int t = 0; t < T_; t++) {
        float emb0 = __ldg(embrow + t * H_ + tid);
        float emb1 = __ldg(embrow + t * H_ + tid + 64);

        // ---- Phase B ----
        {
            float d0 = 0.f, d1 = 0.f, d2 = 0.f, d3 = 0.f;
            #pragma unroll
            for (int i = 0; i < 4; i++) {
                float hv = sh_hs[lane + 32 * i];
                d0 += hv * wbr[0][i]; d1 += hv * wbr[1][i];
                d2 += hv * wbr[2][i]; d3 += hv * wbr[3][i];
            }
            d0 += __shfl_xor_sync(FULLMASK, d0, 16); d1 += __shfl_xor_sync(FULLMASK, d1, 16);
            d2 += __shfl_xor_sync(FULLMASK, d2, 16); d3 += __shfl_xor_sync(FULLMASK, d3, 16);
            d0 += __shfl_xor_sync(FULLMASK, d0, 8);  d1 += __shfl_xor_sync(FULLMASK, d1, 8);
            d2 += __shfl_xor_sync(FULLMASK, d2, 8);  d3 += __shfl_xor_sync(FULLMASK, d3, 8);
            float v = (pgrp == 0) ? d0 : (pgrp == 1) ? d1 : (pgrp == 2) ? d2 : d3;
            v += __shfl_xor_sync(FULLMASK, v, 4);
            v += __shfl_xor_sync(FULLMASK, v, 2);
            v += __shfl_xor_sync(FULLMASK, v, 1);
            if (pjlane) {
                ((float*)&sh_pj4[w])[pgrp] = v + pj_carry;
                pj_carry = pjp[(t + 1) * 8 + w * 4 + pgrp];   // pad-safe overrun at t=127
            }
        }
        __syncthreads();

        // ---- mini-LN(8) + angles (redundant per warp) ----
        float scl;
        float F0[8], F1[8];
        {
            int q = lane & 7;
            float pv = tanhff(((const float*)sh_pj4)[q]);
            float sm_ = pv, sq = pv*pv;
            sm_ += __shfl_xor_sync(FULLMASK, sm_, 1); sq += __shfl_xor_sync(FULLMASK, sq, 1);
            sm_ += __shfl_xor_sync(FULLMASK, sm_, 2); sq += __shfl_xor_sync(FULLMASK, sq, 2);
            sm_ += __shfl_xor_sync(FULLMASK, sm_, 4); sq += __shfl_xor_sync(FULLMASK, sq, 4);
            float mm = sm_ * 0.125f;
            float iv = rsqrtf(sq * 0.125f - mm*mm + EPS_);
            float a = 0.5f * ((pv - mm) * iv * sh_ing8[q] + sh_inb8[q]);
            float ss, cc; __sincosf(a, &ss, &cc);
            float tq = __fdividef(ss, cc);
            cc *= __shfl_xor_sync(FULLMASK, cc, 1);
            cc *= __shfl_xor_sync(FULLMASK, cc, 2);
            cc *= __shfl_xor_sync(FULLMASK, cc, 4);
            float cin = cc * 0.0625f;
            scl = cin * cin * cw2g;
            int base = lane & 24;
            #pragma unroll
            for (int q2 = 0; q2 < 8; q2++) {
                float tg = __shfl_sync(FULLMASK, tq, base | q2);
                F0[q2] = 1.f - tg; F1[q2] = 1.f + tg;
            }
        }

        // ---- Phase C: VQC (tan-form, virtual perm, f32x2) ----
        float2 st2[8];
        {
            float v0 = ((ll&8)?F1[0]:F0[0]) * ((ll&4)?F1[1]:F0[1])
                     * ((ll&2)?F1[2]:F0[2]) * ((ll&1)?F1[3]:F0[3]);
            float a0 = v0 * F0[4], a8 = v0 * F1[4];
            float b0 = a0*F0[5], b4 = a0*F1[5], b8 = a8*F0[5], b12 = a8*F1[5];
            float c0=b0*F0[6], c2=b0*F1[6], c4=b4*F0[6], c6=b4*F1[6];
            float c8=b8*F0[6], c10=b8*F1[6], c12=b12*F0[6], c14=b12*F1[6];
            st2[0]=make_float2(c0*F0[7],  c0*F1[7]);  st2[1]=make_float2(c2*F0[7],  c2*F1[7]);
            st2[2]=make_float2(c4*F0[7],  c4*F1[7]);  st2[3]=make_float2(c6*F0[7],  c6*F1[7]);
            st2[4]=make_float2(c8*F0[7],  c8*F1[7]);  st2[5]=make_float2(c10*F0[7], c10*F1[7]);
            st2[6]=make_float2(c12*F0[7], c12*F1[7]); st2[7]=make_float2(c14*F0[7], c14*F1[7]);
        }

        const int BM[4][4] = {{12,7,3,1},{11,5,2,1},{14,6,3,1},{8,4,2,1}};
        #pragma unroll
        for (int lyr = 0; lyr < 4; lyr++) {
            // c4
            { float2 tp = st2[4]; st2[4] = st2[6]; st2[6] = tp;
              tp = st2[5]; st2[5] = st2[7]; st2[7] = tp; }
            // c6
            { float tp;
              tp = st2[1].x; st2[1].x = st2[1].y; st2[1].y = tp;
              tp = st2[3].x; st2[3].x = st2[3].y; st2[3].y = tp;
              tp = st2[5].x; st2[5].x = st2[5].y; st2[5].y = tp;
              tp = st2[7].x; st2[7].x = st2[7].y; st2[7].y = tp; }
            // c5
            { float2 tp = st2[2]; st2[2] = st2[3]; st2[3] = tp;
              tp = st2[6]; st2[6] = st2[7]; st2[7] = tp; }
            // c3 (virtual-layout parity control)
            {
                bool cc3 = c3b[lyr];
                #pragma unroll
                for (int j = 0; j < 4; j++) {
                    float2 a = st2[j], b = st2[j+4];
                    st2[j].x   = cc3 ? b.x : a.x;  st2[j].y   = cc3 ? b.y : a.y;
                    st2[j+4].x = cc3 ? a.x : b.x;  st2[j+4].y = cc3 ? a.y : b.y;
                }
            }
            // lane-qubit RYs q0..q3
            #pragma unroll
            for (int q = 0; q < 4; q++) {
                const int bm = BM[lyr][q];
                float tq = stp[lyr*4+q];
                #pragma unroll
                for (int j = 0; j < 8; j++) {
                    float ox = __shfl_xor_sync(FULLMASK, st2[j].x, bm);
                    float oy = __shfl_xor_sync(FULLMASK, st2[j].y, bm);
                    st2[j].x = fmaf(tq, ox, st2[j].x);
                    st2[j].y = fmaf(tq, oy, st2[j].y);
                }
            }
            // reg-qubit RYs q4..q7 (f32x2 for q4,q5,q6)
            const float4 tl = *(const float4*)&sh_wct[gate][lyr][4];
            {
                float2 nt = make_float2(-tl.x, -tl.x), pt = make_float2(tl.x, tl.x);
                #pragma unroll
                for (int j = 0; j < 4; j++) {
                    float2 lo = st2[j], hi = st2[j+4];
                    st2[j]   = ffma2(nt, hi, lo);
                    st2[j+4] = ffma2(pt, lo, hi);
                }
            }
            {
                float2 nt = make_float2(-tl.y, -tl.y), pt = make_float2(tl.y, tl.y);
                #pragma unroll
                for (int j = 0; j < 8; j++) if (!(j & 2)) {
                    float2 lo = st2[j], hi = st2[j+2];
                    st2[j]   = ffma2(nt, hi, lo);
                    st2[j+2] = ffma2(pt, lo, hi);
                }
            }
            {
                float2 nt = make_float2(-tl.z, -tl.z), pt = make_float2(tl.z, tl.z);
                #pragma unroll
                for (int j = 0; j < 8; j += 2) {
                    float2 lo = st2[j], hi = st2[j+1];
                    st2[j]   = ffma2(nt, hi, lo);
                    st2[j+1] = ffma2(pt, lo, hi);
                }
            }
            {
                float tq = tl.w;
                #pragma unroll
                for (int j = 0; j < 8; j++) {
                    float a0 = st2[j].x, a1 = st2[j].y;
                    st2[j].x = fmaf(-tq, a1, a0);
                    st2[j].y = fmaf( tq, a0, a1);
                }
            }
        }

        // ---- measurement ----
        {
            float2 p2[8];
            #pragma unroll
            for (int j = 0; j < 8; j++) p2[j] = fmul2(st2[j], st2[j]);
            float s8[8], s4[4], s2[2];
            float z7=0, z6=0, z5=0;
            #pragma unroll
            for (int k = 0; k < 8; k++) { s8[k] = p2[k].x + p2[k].y; z7 += p2[k].x - p2[k].y; }
            #pragma unroll
            for (int k = 0; k < 4; k++) { s4[k] = s8[2*k]+s8[2*k+1]; z6 += s8[2*k]-s8[2*k+1]; }
            #pragma unroll
            for (int k = 0; k < 2; k++) { s2[k] = s4[2*k]+s4[2*k+1]; z5 += s4[2*k]-s4[2*k+1]; }
            float z4 = s2[0]-s2[1], Tt = s2[0]+s2[1];
            float o, z0v, z1v, z2v, z3v;

            o = __shfl_xor_sync(FULLMASK, Tt, 1);
            z3v = (lane & 1) ? (o - Tt) : (Tt - o); Tt += o;
            z4 += __shfl_xor_sync(FULLMASK, z4, 1);
            z5 += __shfl_xor_sync(FULLMASK, z5, 1);
            z6 += __shfl_xor_sync(FULLMASK, z6, 1);
            z7 += __shfl_xor_sync(FULLMASK, z7, 1);

            o = __shfl_xor_sync(FULLMASK, Tt, 2);
            z2v = (lane & 2) ? (o - Tt) : (Tt - o); Tt += o;
            z3v += __shfl_xor_sync(FULLMASK, z3v, 2);
            z4 += __shfl_xor_sync(FULLMASK, z4, 2);
            z5 += __shfl_xor_sync(FULLMASK, z5, 2);
            z6 += __shfl_xor_sync(FULLMASK, z6, 2);
            z7 += __shfl_xor_sync(FULLMASK, z7, 2);

            o = __shfl_xor_sync(FULLMASK, Tt, 4);
            z1v = (lane & 4) ? (o - Tt) : (Tt - o); Tt += o;
            z2v += __shfl_xor_sync(FULLMASK, z2v, 4);
            z3v += __shfl_xor_sync(FULLMASK, z3v, 4);
            z4 += __shfl_xor_sync(FULLMASK, z4, 4);
            z5 += __shfl_xor_sync(FULLMASK, z5, 4);
            z6 += __shfl_xor_sync(FULLMASK, z6, 4);
            z7 += __shfl_xor_sync(FULLMASK, z7, 4);

            o = __shfl_xor_sync(FULLMASK, Tt, 8);
            z0v = (lane & 8) ? (o - Tt) : (Tt - o);
            z1v += __shfl_xor_sync(FULLMASK, z1v, 8);
            z2v += __shfl_xor_sync(FULLMASK, z2v, 8);
            z3v += __shfl_xor_sync(FULLMASK, z3v, 8);
            z4 += __shfl_xor_sync(FULLMASK, z4, 8);
            z5 += __shfl_xor_sync(FULLMASK, z5, 8);
            z6 += __shfl_xor_sync(FULLMASK, z6, 8);
            z7 += __shfl_xor_sync(FULLMASK, z7, 8);

            if (ll == 0) {
                sh_z[gate][0] = make_float4(z0v*scl, z1v*scl, z2v*scl, z3v*scl);
                sh_z[gate][1] = make_float4(z4*scl, z5*scl, z6*scl, z7*scl);
            }
        }
        __syncthreads();

        // ---- Phase D ----
        {
            float4 zr[4][2];
            #pragma unroll
            for (int g = 0; g < 4; g++) { zr[g][0] = sh_z[g][0]; zr[g][1] = sh_z[g][1]; }
            float v[2];
            #pragma unroll
            for (int hh = 0; hh < 2; hh++) {
                float pre[4];
                #pragma unroll
                for (int g = 0; g < 4; g++) {
                    float4 z0 = zr[g][0], z1 = zr[g][1];
                    const float* pw = &pwr[hh][g*8];
                    pre[g] = bia[hh][g]
                           + z0.x*pw[0] + z0.y*pw[1] + z0.z*pw[2] + z0.w*pw[3]
                           + z1.x*pw[4] + z1.y*pw[5] + z1.z*pw[6] + z1.w*pw[7];
                }
                float i_t = sigf(pre[0]);
                float f_t = sigf(pre[1]);
                float g_t = tanhff(pre[2]);
                float o_t = sigf(pre[3]);
                c_c[hh] = f_t*c_c[hh] + i_t*g_t;
                h_c[hh] = o_t*tanhff(c_c[hh]);
                v[hh] = h_c[hh] + (hh ? emb1 : emb0);
            }
            sh_hs[tid] = h_c[0]; sh_hs[tid + 64] = h_c[1];
            float r0 = v[0] + v[1];
            float r1 = v[0]*v[0] + v[1]*v[1];
            float r2 = v[0]*gw0 + v[1]*gw1;
            r0 += __shfl_xor_sync(FULLMASK, r0, 16);
            r1 += __shfl_xor_sync(FULLMASK, r1, 16);
            r2 += __shfl_xor_sync(FULLMASK, r2, 16);
            r0 += __shfl_xor_sync(FULLMASK, r0, 8);
            r1 += __shfl_xor_sync(FULLMASK, r1, 8);
            r2 += __shfl_xor_sync(FULLMASK, r2, 8);
            float vv = (pgrp == 0) ? r0 : (pgrp == 1) ? r1 : r2;
            vv += __shfl_xor_sync(FULLMASK, vv, 4);
            vv += __shfl_xor_sync(FULLMASK, vv, 2);
            vv += __shfl_xor_sync(FULLMASK, vv, 1);
            if (pjlane && pgrp < 3) sh_redf[w][pgrp] = vv;
        }
        __syncthreads();
        if (tid == 0) {
            float Sv = sh_redf[0][0] + sh_redf[1][0];
            float Sq = sh_redf[0][1] + sh_redf[1][1];
            float Sg = sh_redf[0][2] + sh_redf[1][2];
            float m2 = Sv * (1.f/128.f);
            float inv2 = rsqrtf(Sq * (1.f/128.f) - m2*m2 + EPS_);
            out[(size_t)e * T_ + t] = inv2 * (Sg - m2 * S1) + C0;
        }
    }
}

extern "C" void kernel_launch(void* const* d_in, const int* in_sizes, int n_in,
                              void* d_out, int out_size) {
    const float* p[26];
    for (int i = 0; i < 26; i++) p[i] = (const float*)d_in[i];
    emb_pj_kernel<<<1024, 128>>>(p[0], p[1], p[2], p[3], p[4], p[5], p[6], p[7]);
    qlstm_kernel<<<1024, 64>>>(
        p[6], p[8], p[9], p[10], p[11], p[12], p[13],
        p[14], p[15], p[16], p[17], p[18], p[19], p[20], p[21],
        p[22], p[23], p[24], p[25], (float*)d_out);
}